// round 5
// baseline (speedup 1.0000x reference)
#include <cuda_runtime.h>
#include <mma.h>
#include <math.h>

using namespace nvcuda;

#define Bsz 2
#define Lq  2048
#define Dm  256
#define Hh  8
#define hd  32
#define CH  128
#define NCH 16
#define BHn (Bsz*Hh)
#define EPSf 1e-5f

// ---- scratch (device globals; no allocations allowed) ----
__device__ float g_q[BHn*Lq*hd];
__device__ float g_k[BHn*Lq*hd];
__device__ float g_v[BHn*Lq*hd];
__device__ float g_sim[BHn*Lq];
__device__ float g_gate[BHn*Lq];
__device__ float g_Sc[BHn*NCH*hd*hd];
__device__ float g_gsum[BHn*NCH];
__device__ float g_mc[BHn*NCH];
__device__ float g_scC[BHn*NCH];
__device__ float g_ctx[Bsz*Lq*Dm];

__device__ __forceinline__ float warpSum(float v) {
    #pragma unroll
    for (int o = 16; o; o >>= 1) v += __shfl_xor_sync(0xffffffffu, v, o);
    return v;
}
__device__ __forceinline__ float tf32r(float f) { return wmma::__float_to_tf32(f); }

// ============================================================
// K1: QKV projection, 3xTF32 (error-compensated).
// BM=BN=64, BK=32, 256 threads = 8 warps (2x4), warp tile 32x16.
// grid: (4096/64=64, 12). by>>2 selects matrix, by&3 selects n-block.
// ============================================================
__global__ void k_qkv(const float* __restrict__ x,
                      const float* __restrict__ wq, const float* __restrict__ bq,
                      const float* __restrict__ wk, const float* __restrict__ bk,
                      const float* __restrict__ wv, const float* __restrict__ bv)
{
    __shared__ float buf[10240];              // Ah,Al,Bh,Bl each 64x40
    float* Ah = buf;
    float* Al = buf + 2560;
    float* Bh = buf + 5120;
    float* Bl = buf + 7680;
    const int t   = threadIdx.x;
    const int m0  = blockIdx.x * 64;
    const int mat = blockIdx.y >> 2;
    const int n0  = (blockIdx.y & 3) * 64;
    const float* W    = (mat == 0) ? wq : ((mat == 1) ? wk : wv);
    const float* bias = (mat == 0) ? bq : ((mat == 1) ? bk : bv);

    const int warp = t >> 5;
    const int wm = warp >> 2, wn = warp & 3;

    wmma::fragment<wmma::accumulator, 16, 16, 8, float> c[2];
    wmma::fill_fragment(c[0], 0.0f);
    wmma::fill_fragment(c[1], 0.0f);

    const int lrow = t >> 3, lcol = (t & 7) * 4;
    for (int k0 = 0; k0 < 256; k0 += 32) {
        __syncthreads();
        #pragma unroll
        for (int r = 0; r < 2; r++) {
            int row = lrow + r*32;
            float4 a4 = *(const float4*)(x + (m0 + row)*256 + k0 + lcol);
            float4 b4 = *(const float4*)(W + (n0 + row)*256 + k0 + lcol);
            float* ah = &Ah[row*40 + lcol]; float* al = &Al[row*40 + lcol];
            float* bh = &Bh[row*40 + lcol]; float* bl = &Bl[row*40 + lcol];
            float h;
            h = tf32r(a4.x); ah[0] = h; al[0] = tf32r(a4.x - h);
            h = tf32r(a4.y); ah[1] = h; al[1] = tf32r(a4.y - h);
            h = tf32r(a4.z); ah[2] = h; al[2] = tf32r(a4.z - h);
            h = tf32r(a4.w); ah[3] = h; al[3] = tf32r(a4.w - h);
            h = tf32r(b4.x); bh[0] = h; bl[0] = tf32r(b4.x - h);
            h = tf32r(b4.y); bh[1] = h; bl[1] = tf32r(b4.y - h);
            h = tf32r(b4.z); bh[2] = h; bl[2] = tf32r(b4.z - h);
            h = tf32r(b4.w); bh[3] = h; bl[3] = tf32r(b4.w - h);
        }
        __syncthreads();
        #pragma unroll
        for (int kk = 0; kk < 4; kk++) {
            wmma::fragment<wmma::matrix_a, 16, 16, 8, wmma::precision::tf32, wmma::row_major> ah[2], al[2];
            wmma::fragment<wmma::matrix_b, 16, 16, 8, wmma::precision::tf32, wmma::col_major> bh, bl;
            #pragma unroll
            for (int i = 0; i < 2; i++) {
                wmma::load_matrix_sync(ah[i], &Ah[(wm*32 + i*16)*40 + kk*8], 40);
                wmma::load_matrix_sync(al[i], &Al[(wm*32 + i*16)*40 + kk*8], 40);
            }
            wmma::load_matrix_sync(bh, &Bh[(wn*16)*40 + kk*8], 40);
            wmma::load_matrix_sync(bl, &Bl[(wn*16)*40 + kk*8], 40);
            #pragma unroll
            for (int i = 0; i < 2; i++) {
                wmma::mma_sync(c[i], ah[i], bh, c[i]);
                wmma::mma_sync(c[i], al[i], bh, c[i]);
                wmma::mma_sync(c[i], ah[i], bl, c[i]);
            }
        }
    }
    __syncthreads();
    float* Cs = buf;                           // 64x64
    #pragma unroll
    for (int i = 0; i < 2; i++)
        wmma::store_matrix_sync(&Cs[(wm*32 + i*16)*64 + wn*16], c[i], 64, wmma::mem_row_major);
    __syncthreads();
    float* dst = (mat == 0) ? g_q : ((mat == 1) ? g_k : g_v);
    for (int idx = t; idx < 64*64; idx += 256) {
        int row = idx >> 6, col = idx & 63;
        int m = m0 + row;
        int b = m >> 11, l = m & 2047;
        int o = n0 + col;
        int hidx = o >> 5, d = o & 31;
        dst[((b*Hh + hidx)*Lq + l)*hd + d] = Cs[idx] + bias[o];
    }
}

// ============================================================
// K2: fused per-position preprocess + per-chunk sums (fp32).
// grid: BHn*NCH = 256 blocks, 256 threads.
// ============================================================
__global__ void k_prepchunk(const float* __restrict__ wg, const float* __restrict__ wgb,
                            const float* __restrict__ kvs, const float* __restrict__ qks)
{
    __shared__ float Ks[CH*hd];
    __shared__ float Vs[CH*hd];
    __shared__ float Ms[32*33];
    __shared__ float gs[CH], sims[CH];
    const int tid = threadIdx.x;
    const int bx  = blockIdx.x;
    const int bh  = bx >> 4, c = bx & 15;
    const int h   = bh & 7;
    for (int idx = tid; idx < 1024; idx += 256) {
        int d = idx >> 5, e = idx & 31;
        Ms[d*33 + e] = kvs[h*1024 + idx] * wg[idx];
    }
    __syncthreads();
    const float qscale = qks[h];
    const float wb0    = wgb[0];
    const int warp = tid >> 5, lane = tid & 31;
    for (int jj = 0; jj < 16; jj++) {
        int pos  = warp*16 + jj;
        int l    = c*CH + pos;
        int base = (bh*Lq + l)*hd + lane;
        float qd = g_q[base], kd = g_k[base], vd = g_v[base];
        float sim = warpSum(qd*kd) * qscale;
        float kh  = kd / fmaxf(sqrtf(warpSum(kd*kd)), 1e-12f);
        float vh  = vd / fmaxf(sqrtf(warpSum(vd*vd)), 1e-12f);
        Ks[pos*hd + lane] = kh;
        Vs[pos*hd + lane] = vh;
        g_k[base] = kh;
        g_v[base] = vh;
        __syncwarp();
        float td = 0.f;
        #pragma unroll
        for (int e = 0; e < 32; e++)
            td += Ms[lane*33 + e] * Ks[pos*hd + e];
        float logit = warpSum(vh*td) + wb0;
        float r = fmaxf(logit, 0.f);
        float gate = r*r + EPSf;
        if (lane == 0) {
            gs[pos] = gate; sims[pos] = sim;
            g_gate[bh*Lq + l] = gate; g_sim[bh*Lq + l] = sim;
        }
    }
    __syncthreads();
    const int d = tid >> 3, e0 = (tid & 7) * 4;
    float4 acc = {0.f, 0.f, 0.f, 0.f};
    for (int i = 0; i < CH; i++) {
        float cfv = gs[i] * Vs[i*hd + d];
        float4 k4 = *(float4*)&Ks[i*hd + e0];
        acc.x += cfv*k4.x; acc.y += cfv*k4.y; acc.z += cfv*k4.z; acc.w += cfv*k4.w;
    }
    *(float4*)&g_Sc[bx*1024 + tid*4] = acc;
    if (tid < 32) {
        float m = -1e30f;
        #pragma unroll
        for (int k = 0; k < 4; k++) m = fmaxf(m, sims[tid + 32*k]);
        #pragma unroll
        for (int o = 16; o; o >>= 1) m = fmaxf(m, __shfl_xor_sync(0xffffffffu, m, o));
        float s = 0.f, gsum = 0.f;
        #pragma unroll
        for (int k = 0; k < 4; k++) { s += __expf(sims[tid + 32*k] - m); gsum += gs[tid + 32*k]; }
        s = warpSum(s); gsum = warpSum(gsum);
        if (tid == 0) { g_mc[bx] = m; g_scC[bx] = s; g_gsum[bx] = gsum; }
    }
}

// ============================================================
// K3: intra-chunk via tf32 tensor cores + scalar scans.
// grid BHn*NCH = 256 blocks, 256 threads (8 warps).
// Warp w owns output rows [16w, 16w+16):
//   Y = Q@S_prev + sum_panels mask(g ∘ (Q@V^T)) @ K
// dynamic smem layout (floats):
//   Qs 128x40 | Vs 128x40 | Ks 128x40 | Pan 128x40 | Sps 32x40 | scans 7x128 | misc 4
// ============================================================
#define QS_O   0
#define VS_O   5120
#define KS_O   10240
#define PAN_O  15360
#define SPS_O  20480
#define SCN_O  21760
#define MSC_O  (SCN_O + 7*128)
#define SMEM_INTRA ((MSC_O + 4) * 4)

__global__ void k_intra()
{
    extern __shared__ float sm[];
    float* Qs   = sm + QS_O;
    float* Vs   = sm + VS_O;
    float* Ks   = sm + KS_O;
    float* Pan  = sm + PAN_O;
    float* Sps  = sm + SPS_O;
    float* mA   = sm + SCN_O;
    float* sA   = mA + 128;
    float* gA   = sA + 128;
    float* simA = gA + 128;
    float* rawg = simA + 128;
    float* ws   = rawg + 128;
    float* dinv = ws + 128;
    float* misc = sm + MSC_O;

    const int tid = threadIdx.x;
    const int bx  = blockIdx.x;
    const int bh  = bx >> 4, c = bx & 15;
    const int b   = bh >> 3, h = bh & 7;
    const int gb  = (bh*Lq + c*CH)*hd;

    // exclusive prefix of chunk states (fp32 -> tf32 into Sps)
    {
        int idx = tid*4;
        float4 a = {0.f, 0.f, 0.f, 0.f};
        for (int cc = 0; cc < c; cc++) {
            float4 v = *(const float4*)&g_Sc[(bh*NCH + cc)*1024 + idx];
            a.x += v.x; a.y += v.y; a.z += v.z; a.w += v.w;
        }
        int d = idx >> 5, e0 = idx & 31;
        Sps[d*40 + e0 + 0] = tf32r(a.x);
        Sps[d*40 + e0 + 1] = tf32r(a.y);
        Sps[d*40 + e0 + 2] = tf32r(a.z);
        Sps[d*40 + e0 + 3] = tf32r(a.w);
    }
    if (tid == 0) {
        float m = -1e30f, s = 0.f, ga = 0.f;
        for (int cc = 0; cc < c; cc++) {
            int i = bh*NCH + cc;
            float mc = g_mc[i], sc = g_scC[i];
            float mn = fmaxf(m, mc);
            s = s*__expf(m - mn) + sc*__expf(mc - mn);
            m = mn;
            ga += g_gsum[i];
        }
        misc[0] = m; misc[1] = s; misc[2] = ga;
    }

    // load Q, V, K tiles (convert to tf32)
    for (int idx = tid*4; idx < CH*hd; idx += 1024) {
        int i = idx >> 5, d = idx & 31;
        float4 q4 = *(const float4*)&g_q[gb + idx];
        float4 v4 = *(const float4*)&g_v[gb + idx];
        float4 k4 = *(const float4*)&g_k[gb + idx];
        float* qd = &Qs[i*40 + d]; float* vd = &Vs[i*40 + d]; float* kd = &Ks[i*40 + d];
        qd[0]=tf32r(q4.x); qd[1]=tf32r(q4.y); qd[2]=tf32r(q4.z); qd[3]=tf32r(q4.w);
        vd[0]=tf32r(v4.x); vd[1]=tf32r(v4.y); vd[2]=tf32r(v4.z); vd[3]=tf32r(v4.w);
        kd[0]=tf32r(k4.x); kd[1]=tf32r(k4.y); kd[2]=tf32r(k4.z); kd[3]=tf32r(k4.w);
    }
    if (tid < CH) {
        float sv = g_sim [bh*Lq + c*CH + tid];
        float gv = g_gate[bh*Lq + c*CH + tid];
        mA[tid] = sv; simA[tid] = sv; sA[tid] = 1.f; gA[tid] = gv; rawg[tid] = gv;
    }
    __syncthreads();

    // Hillis-Steele inclusive scans within chunk
    for (int off = 1; off < CH; off <<= 1) {
        float m2 = 0.f, s2 = 0.f, g2 = 0.f;
        bool act = (tid < CH) && (tid >= off);
        if (act) { m2 = mA[tid-off]; s2 = sA[tid-off]; g2 = gA[tid-off]; }
        __syncthreads();
        if (act) {
            float mn = fmaxf(mA[tid], m2);
            sA[tid] = sA[tid]*__expf(mA[tid] - mn) + s2*__expf(m2 - mn);
            mA[tid] = mn;
            gA[tid] += g2;
        }
        __syncthreads();
    }
    if (tid < CH) {
        float mp = misc[0], sp = misc[1], gp = misc[2];
        float mn = fmaxf(mp, mA[tid]);
        float st = sp*__expf(mp - mn) + sA[tid]*__expf(mA[tid] - mn);
        float sw = __expf(simA[tid] - mn) / (st + EPSf);
        ws[tid]   = 1.f + sw / (1.f + __expf(-sw));
        dinv[tid] = 1.f / (gp + gA[tid] + EPSf);
    }
    __syncthreads();

    // ---- tensor-core phase: each warp owns rows [16w, 16w+16) ----
    const int warp = tid >> 5, lane = tid & 31;
    const int r0 = warp * 16;
    float* myPan = &Pan[r0*40];

    wmma::fragment<wmma::accumulator, 16, 16, 8, float> cY[2];
    // Y2 = Q @ S_prev
    {
        wmma::fill_fragment(cY[0], 0.0f);
        wmma::fill_fragment(cY[1], 0.0f);
        #pragma unroll
        for (int kk = 0; kk < 4; kk++) {
            wmma::fragment<wmma::matrix_a, 16, 16, 8, wmma::precision::tf32, wmma::row_major> a;
            wmma::load_matrix_sync(a, &Qs[r0*40 + kk*8], 40);
            #pragma unroll
            for (int jn = 0; jn < 2; jn++) {
                wmma::fragment<wmma::matrix_b, 16, 16, 8, wmma::precision::tf32, wmma::row_major> bm;
                wmma::load_matrix_sync(bm, &Sps[(kk*8)*40 + jn*16], 40);
                wmma::mma_sync(cY[jn], a, bm, cY[jn]);
            }
        }
    }
    // panels of i: [32j, 32j+32)
    for (int j = 0; j * 32 <= r0 + 15; j++) {
        // P panel = Q(rows r0..r0+15) @ V^T(cols 32j..32j+31)
        wmma::fragment<wmma::accumulator, 16, 16, 8, float> cP[2];
        wmma::fill_fragment(cP[0], 0.0f);
        wmma::fill_fragment(cP[1], 0.0f);
        #pragma unroll
        for (int kk = 0; kk < 4; kk++) {
            wmma::fragment<wmma::matrix_a, 16, 16, 8, wmma::precision::tf32, wmma::row_major> a;
            wmma::load_matrix_sync(a, &Qs[r0*40 + kk*8], 40);
            #pragma unroll
            for (int jn = 0; jn < 2; jn++) {
                wmma::fragment<wmma::matrix_b, 16, 16, 8, wmma::precision::tf32, wmma::col_major> bm;
                wmma::load_matrix_sync(bm, &Vs[(j*32 + jn*16)*40 + kk*8], 40);
                wmma::mma_sync(cP[jn], a, bm, cP[jn]);
            }
        }
        wmma::store_matrix_sync(&myPan[0],  cP[0], 40, wmma::mem_row_major);
        wmma::store_matrix_sync(&myPan[16], cP[1], 40, wmma::mem_row_major);
        __syncwarp();
        // mask (i<=r) and gate-scale, convert to tf32
        #pragma unroll
        for (int e = 0; e < 16; e++) {
            int idx = lane + e*32;            // 512 elements: 16 rows x 32 cols
            int rr = idx >> 5, ii = idx & 31;
            int rgl = r0 + rr, igl = j*32 + ii;
            float val = myPan[rr*40 + ii];
            val = (igl <= rgl) ? rawg[igl] * val : 0.f;
            myPan[rr*40 + ii] = tf32r(val);
        }
        __syncwarp();
        // Y += cf_panel @ K(rows 32j..32j+31)
        #pragma unroll
        for (int kk = 0; kk < 4; kk++) {
            wmma::fragment<wmma::matrix_a, 16, 16, 8, wmma::precision::tf32, wmma::row_major> a;
            wmma::load_matrix_sync(a, &myPan[kk*8], 40);
            #pragma unroll
            for (int jn = 0; jn < 2; jn++) {
                wmma::fragment<wmma::matrix_b, 16, 16, 8, wmma::precision::tf32, wmma::row_major> bm;
                wmma::load_matrix_sync(bm, &Ks[(j*32 + kk*8)*40 + jn*16], 40);
                wmma::mma_sync(cY[jn], a, bm, cY[jn]);
            }
        }
        __syncwarp();
    }
    // write out: y * ws * dinv
    wmma::store_matrix_sync(&myPan[0],  cY[0], 40, wmma::mem_row_major);
    wmma::store_matrix_sync(&myPan[16], cY[1], 40, wmma::mem_row_major);
    __syncwarp();
    #pragma unroll
    for (int rr = 0; rr < 16; rr++) {
        int r = r0 + rr;
        float y = myPan[rr*40 + lane] * ws[r] * dinv[r];
        g_ctx[(b*Lq + c*CH + r)*Dm + h*hd + lane] = y;
    }
}

// ============================================================
// K4: output projection, 3xTF32. out = ctx @ wo^T + bo
// BM=BN=64, grid (64,4).
// ============================================================
__global__ void k_out(const float* __restrict__ wo, const float* __restrict__ bo,
                      float* __restrict__ out)
{
    __shared__ float buf[10240];
    float* Ah = buf;
    float* Al = buf + 2560;
    float* Bh = buf + 5120;
    float* Bl = buf + 7680;
    const int t  = threadIdx.x;
    const int m0 = blockIdx.x * 64;
    const int n0 = blockIdx.y * 64;
    const int warp = t >> 5;
    const int wm = warp >> 2, wn = warp & 3;

    wmma::fragment<wmma::accumulator, 16, 16, 8, float> c[2];
    wmma::fill_fragment(c[0], 0.0f);
    wmma::fill_fragment(c[1], 0.0f);

    const int lrow = t >> 3, lcol = (t & 7) * 4;
    for (int k0 = 0; k0 < 256; k0 += 32) {
        __syncthreads();
        #pragma unroll
        for (int r = 0; r < 2; r++) {
            int row = lrow + r*32;
            float4 a4 = *(const float4*)(g_ctx + (m0 + row)*256 + k0 + lcol);
            float4 b4 = *(const float4*)(wo    + (n0 + row)*256 + k0 + lcol);
            float* ah = &Ah[row*40 + lcol]; float* al = &Al[row*40 + lcol];
            float* bh = &Bh[row*40 + lcol]; float* bl = &Bl[row*40 + lcol];
            float hh;
            hh = tf32r(a4.x); ah[0] = hh; al[0] = tf32r(a4.x - hh);
            hh = tf32r(a4.y); ah[1] = hh; al[1] = tf32r(a4.y - hh);
            hh = tf32r(a4.z); ah[2] = hh; al[2] = tf32r(a4.z - hh);
            hh = tf32r(a4.w); ah[3] = hh; al[3] = tf32r(a4.w - hh);
            hh = tf32r(b4.x); bh[0] = hh; bl[0] = tf32r(b4.x - hh);
            hh = tf32r(b4.y); bh[1] = hh; bl[1] = tf32r(b4.y - hh);
            hh = tf32r(b4.z); bh[2] = hh; bl[2] = tf32r(b4.z - hh);
            hh = tf32r(b4.w); bh[3] = hh; bl[3] = tf32r(b4.w - hh);
        }
        __syncthreads();
        #pragma unroll
        for (int kk = 0; kk < 4; kk++) {
            wmma::fragment<wmma::matrix_a, 16, 16, 8, wmma::precision::tf32, wmma::row_major> ah[2], al[2];
            wmma::fragment<wmma::matrix_b, 16, 16, 8, wmma::precision::tf32, wmma::col_major> bh, bl;
            #pragma unroll
            for (int i = 0; i < 2; i++) {
                wmma::load_matrix_sync(ah[i], &Ah[(wm*32 + i*16)*40 + kk*8], 40);
                wmma::load_matrix_sync(al[i], &Al[(wm*32 + i*16)*40 + kk*8], 40);
            }
            wmma::load_matrix_sync(bh, &Bh[(wn*16)*40 + kk*8], 40);
            wmma::load_matrix_sync(bl, &Bl[(wn*16)*40 + kk*8], 40);
            #pragma unroll
            for (int i = 0; i < 2; i++) {
                wmma::mma_sync(c[i], ah[i], bh, c[i]);
                wmma::mma_sync(c[i], al[i], bh, c[i]);
                wmma::mma_sync(c[i], ah[i], bl, c[i]);
            }
        }
    }
    __syncthreads();
    float* Cs = buf;
    #pragma unroll
    for (int i = 0; i < 2; i++)
        wmma::store_matrix_sync(&Cs[(wm*32 + i*16)*64 + wn*16], c[i], 64, wmma::mem_row_major);
    __syncthreads();
    for (int idx = t; idx < 64*64; idx += 256) {
        int row = idx >> 6, col = idx & 63;
        int o = n0 + col;
        out[(m0 + row)*256 + o] = Cs[idx] + bo[o];
    }
}

// ============================================================
extern "C" void kernel_launch(void* const* d_in, const int* in_sizes, int n_in,
                              void* d_out, int out_size)
{
    const float* x   = (const float*)d_in[0];
    const float* wq  = (const float*)d_in[1];
    const float* bq  = (const float*)d_in[2];
    const float* wk  = (const float*)d_in[3];
    const float* bk  = (const float*)d_in[4];
    const float* wv  = (const float*)d_in[5];
    const float* bv  = (const float*)d_in[6];
    const float* wo  = (const float*)d_in[7];
    const float* bo  = (const float*)d_in[8];
    const float* wg  = (const float*)d_in[9];
    const float* wgb = (const float*)d_in[10];
    const float* kvs = (const float*)d_in[11];
    const float* qks = (const float*)d_in[12];
    float* out = (float*)d_out;

    cudaFuncSetAttribute(k_intra, cudaFuncAttributeMaxDynamicSharedMemorySize, SMEM_INTRA);

    k_qkv      <<<dim3(64, 12), 256>>>(x, wq, bq, wk, bk, wv, bv);
    k_prepchunk<<<256, 256>>>(wg, wgb, kvs, qks);
    k_intra    <<<256, 256, SMEM_INTRA>>>();
    k_out      <<<dim3(64, 4), 256>>>(wo, bo, out);
}

// round 7
// speedup vs baseline: 2.1405x; 2.1405x over previous
#include <cuda_runtime.h>
#include <cuda_fp16.h>
#include <mma.h>
#include <math.h>

using namespace nvcuda;

#define Bsz 2
#define Lq  2048
#define Dm  256
#define Hh  8
#define hd  32
#define CH  128
#define NCH 16
#define BHn (Bsz*Hh)
#define EPSf 1e-5f

// ---- scratch (device globals; no allocations allowed) ----
__device__ float g_q[BHn*Lq*hd];
__device__ float g_k[BHn*Lq*hd];
__device__ float g_v[BHn*Lq*hd];
__device__ float g_sim[BHn*Lq];
__device__ float g_gate[BHn*Lq];
__device__ float g_Sc[BHn*NCH*hd*hd];
__device__ float g_gsum[BHn*NCH];
__device__ float g_mc[BHn*NCH];
__device__ float g_scC[BHn*NCH];
__device__ float g_ctx[Bsz*Lq*Dm];

__device__ __forceinline__ float warpSum(float v) {
    #pragma unroll
    for (int o = 16; o; o >>= 1) v += __shfl_xor_sync(0xffffffffu, v, o);
    return v;
}
__device__ __forceinline__ float tf32r(float f) { return wmma::__float_to_tf32(f); }

// split one float into fp16 hi + fp16 lo (residual)
__device__ __forceinline__ void h_split(float f, __half* hp, __half* lp) {
    __half hi = __float2half_rn(f);
    *hp = hi;
    *lp = __float2half_rn(f - __half2float(hi));
}

// ============================================================
// K1: QKV projection, split-fp16 (3-term error-compensated) HMMA.
// BM=128, BN=64, BK=32. 256 threads = 8 warps (4m x 2n), warp tile 32x32.
// grid: (4096/128=32, 12). by>>2 selects matrix, by&3 selects n-block.
// smem: Ah,Al [128][40] halfs, Bh,Bl [64][40] halfs  (30720 B), Cs reuse.
// ============================================================
#define LDH 40
__global__ void k_qkv(const float* __restrict__ x,
                      const float* __restrict__ wq, const float* __restrict__ bq,
                      const float* __restrict__ wk, const float* __restrict__ bk,
                      const float* __restrict__ wv, const float* __restrict__ bv)
{
    __shared__ __align__(16) unsigned char smraw[32768];
    __half* Ah = (__half*)smraw;                 // 128*40
    __half* Al = Ah + 128*LDH;
    __half* Bh = Al + 128*LDH;                   // 64*40
    __half* Bl = Bh + 64*LDH;
    float*  Cs = (float*)smraw;                  // epilogue reuse (128*64)

    const int t   = threadIdx.x;
    const int m0  = blockIdx.x * 128;
    const int mat = blockIdx.y >> 2;
    const int n0  = (blockIdx.y & 3) * 64;
    const float* W    = (mat == 0) ? wq : ((mat == 1) ? wk : wv);
    const float* bias = (mat == 0) ? bq : ((mat == 1) ? bk : bv);

    const int warp = t >> 5;
    const int wm = warp >> 1, wn = warp & 1;     // 4x2 warps, 32x32 tiles

    wmma::fragment<wmma::accumulator, 16, 16, 16, float> c[2][2];
    #pragma unroll
    for (int i = 0; i < 2; i++)
        #pragma unroll
        for (int j = 0; j < 2; j++) wmma::fill_fragment(c[i][j], 0.0f);

    for (int k0 = 0; k0 < 256; k0 += 32) {
        // A tile: 128x32 -> 1024 float4, 4 per thread
        #pragma unroll
        for (int p = 0; p < 4; p++) {
            int f = t + p*256;
            int row = f >> 3, cc = (f & 7) * 4;
            float4 a4 = *(const float4*)(x + (m0 + row)*256 + k0 + cc);
            int off = row*LDH + cc;
            h_split(a4.x, &Ah[off+0], &Al[off+0]);
            h_split(a4.y, &Ah[off+1], &Al[off+1]);
            h_split(a4.z, &Ah[off+2], &Al[off+2]);
            h_split(a4.w, &Ah[off+3], &Al[off+3]);
        }
        // B tile: 64x32 -> 512 float4, 2 per thread
        #pragma unroll
        for (int p = 0; p < 2; p++) {
            int f = t + p*256;
            int row = f >> 3, cc = (f & 7) * 4;
            float4 b4 = *(const float4*)(W + (n0 + row)*256 + k0 + cc);
            int off = row*LDH + cc;
            h_split(b4.x, &Bh[off+0], &Bl[off+0]);
            h_split(b4.y, &Bh[off+1], &Bl[off+1]);
            h_split(b4.z, &Bh[off+2], &Bl[off+2]);
            h_split(b4.w, &Bh[off+3], &Bl[off+3]);
        }
        __syncthreads();
        #pragma unroll
        for (int kk = 0; kk < 2; kk++) {
            wmma::fragment<wmma::matrix_a, 16, 16, 16, __half, wmma::row_major> ah[2], al[2];
            wmma::fragment<wmma::matrix_b, 16, 16, 16, __half, wmma::col_major> bhf[2], blf[2];
            #pragma unroll
            for (int i = 0; i < 2; i++) {
                wmma::load_matrix_sync(ah[i], &Ah[(wm*32 + i*16)*LDH + kk*16], LDH);
                wmma::load_matrix_sync(al[i], &Al[(wm*32 + i*16)*LDH + kk*16], LDH);
            }
            #pragma unroll
            for (int j = 0; j < 2; j++) {
                wmma::load_matrix_sync(bhf[j], &Bh[(wn*32 + j*16)*LDH + kk*16], LDH);
                wmma::load_matrix_sync(blf[j], &Bl[(wn*32 + j*16)*LDH + kk*16], LDH);
            }
            #pragma unroll
            for (int i = 0; i < 2; i++)
                #pragma unroll
                for (int j = 0; j < 2; j++) {
                    wmma::mma_sync(c[i][j], ah[i], bhf[j], c[i][j]);
                    wmma::mma_sync(c[i][j], al[i], bhf[j], c[i][j]);
                    wmma::mma_sync(c[i][j], ah[i], blf[j], c[i][j]);
                }
        }
        __syncthreads();
    }
    #pragma unroll
    for (int i = 0; i < 2; i++)
        #pragma unroll
        for (int j = 0; j < 2; j++)
            wmma::store_matrix_sync(&Cs[(wm*32 + i*16)*64 + wn*32 + j*16], c[i][j], 64, wmma::mem_row_major);
    __syncthreads();
    float* dst = (mat == 0) ? g_q : ((mat == 1) ? g_k : g_v);
    for (int idx = t; idx < 128*64; idx += 256) {
        int row = idx >> 6, col = idx & 63;
        int m = m0 + row;
        int b = m >> 11, l = m & 2047;
        int o = n0 + col;
        int hidx = o >> 5, d = o & 31;
        dst[((b*Hh + hidx)*Lq + l)*hd + d] = Cs[idx] + bias[o];
    }
}

// ============================================================
// K2: fused per-position preprocess + per-chunk sums (fp32).
// grid: BHn*NCH = 256 blocks, 256 threads.
// ============================================================
__global__ void k_prepchunk(const float* __restrict__ wg, const float* __restrict__ wgb,
                            const float* __restrict__ kvs, const float* __restrict__ qks)
{
    __shared__ float Ks[CH*hd];
    __shared__ float Vs[CH*hd];
    __shared__ float Ms[32*33];
    __shared__ float gs[CH], sims[CH];
    const int tid = threadIdx.x;
    const int bx  = blockIdx.x;
    const int bh  = bx >> 4, c = bx & 15;
    const int h   = bh & 7;
    for (int idx = tid; idx < 1024; idx += 256) {
        int d = idx >> 5, e = idx & 31;
        Ms[d*33 + e] = kvs[h*1024 + idx] * wg[idx];
    }
    __syncthreads();
    const float qscale = qks[h];
    const float wb0    = wgb[0];
    const int warp = tid >> 5, lane = tid & 31;
    for (int jj = 0; jj < 16; jj++) {
        int pos  = warp*16 + jj;
        int l    = c*CH + pos;
        int base = (bh*Lq + l)*hd + lane;
        float qd = g_q[base], kd = g_k[base], vd = g_v[base];
        float sim = warpSum(qd*kd) * qscale;
        float kh  = kd / fmaxf(sqrtf(warpSum(kd*kd)), 1e-12f);
        float vh  = vd / fmaxf(sqrtf(warpSum(vd*vd)), 1e-12f);
        Ks[pos*hd + lane] = kh;
        Vs[pos*hd + lane] = vh;
        g_k[base] = kh;
        g_v[base] = vh;
        __syncwarp();
        float td = 0.f;
        #pragma unroll
        for (int e = 0; e < 32; e++)
            td += Ms[lane*33 + e] * Ks[pos*hd + e];
        float logit = warpSum(vh*td) + wb0;
        float r = fmaxf(logit, 0.f);
        float gate = r*r + EPSf;
        if (lane == 0) {
            gs[pos] = gate; sims[pos] = sim;
            g_gate[bh*Lq + l] = gate; g_sim[bh*Lq + l] = sim;
        }
    }
    __syncthreads();
    const int d = tid >> 3, e0 = (tid & 7) * 4;
    float4 acc = {0.f, 0.f, 0.f, 0.f};
    for (int i = 0; i < CH; i++) {
        float cfv = gs[i] * Vs[i*hd + d];
        float4 k4 = *(float4*)&Ks[i*hd + e0];
        acc.x += cfv*k4.x; acc.y += cfv*k4.y; acc.z += cfv*k4.z; acc.w += cfv*k4.w;
    }
    *(float4*)&g_Sc[bx*1024 + tid*4] = acc;
    if (tid < 32) {
        float m = -1e30f;
        #pragma unroll
        for (int k = 0; k < 4; k++) m = fmaxf(m, sims[tid + 32*k]);
        #pragma unroll
        for (int o = 16; o; o >>= 1) m = fmaxf(m, __shfl_xor_sync(0xffffffffu, m, o));
        float s = 0.f, gsum = 0.f;
        #pragma unroll
        for (int k = 0; k < 4; k++) { s += __expf(sims[tid + 32*k] - m); gsum += gs[tid + 32*k]; }
        s = warpSum(s); gsum = warpSum(gsum);
        if (tid == 0) { g_mc[bx] = m; g_scC[bx] = s; g_gsum[bx] = gsum; }
    }
}

// ============================================================
// K3: intra-chunk via tf32 tensor cores + scalar scans.
// grid BHn*NCH = 256 blocks, 256 threads (8 warps).
// Warp w owns output rows [16w, 16w+16):
//   Y = Q@S_prev + sum_panels mask(g ∘ (Q@V^T)) @ K
// ============================================================
#define QS_O   0
#define VS_O   5120
#define KS_O   10240
#define PAN_O  15360
#define SPS_O  20480
#define SCN_O  21760
#define MSC_O  (SCN_O + 7*128)
#define SMEM_INTRA ((MSC_O + 4) * 4)

__global__ void k_intra()
{
    extern __shared__ float sm[];
    float* Qs   = sm + QS_O;
    float* Vs   = sm + VS_O;
    float* Ks   = sm + KS_O;
    float* Pan  = sm + PAN_O;
    float* Sps  = sm + SPS_O;
    float* mA   = sm + SCN_O;
    float* sA   = mA + 128;
    float* gA   = sA + 128;
    float* simA = gA + 128;
    float* rawg = simA + 128;
    float* ws   = rawg + 128;
    float* dinv = ws + 128;
    float* misc = sm + MSC_O;

    const int tid = threadIdx.x;
    const int bx  = blockIdx.x;
    const int bh  = bx >> 4, c = bx & 15;
    const int b   = bh >> 3, h = bh & 7;
    const int gb  = (bh*Lq + c*CH)*hd;

    // exclusive prefix of chunk states (fp32 -> tf32 into Sps)
    {
        int idx = tid*4;
        float4 a = {0.f, 0.f, 0.f, 0.f};
        for (int cc = 0; cc < c; cc++) {
            float4 v = *(const float4*)&g_Sc[(bh*NCH + cc)*1024 + idx];
            a.x += v.x; a.y += v.y; a.z += v.z; a.w += v.w;
        }
        int d = idx >> 5, e0 = idx & 31;
        Sps[d*40 + e0 + 0] = tf32r(a.x);
        Sps[d*40 + e0 + 1] = tf32r(a.y);
        Sps[d*40 + e0 + 2] = tf32r(a.z);
        Sps[d*40 + e0 + 3] = tf32r(a.w);
    }
    if (tid == 0) {
        float m = -1e30f, s = 0.f, ga = 0.f;
        for (int cc = 0; cc < c; cc++) {
            int i = bh*NCH + cc;
            float mc = g_mc[i], sc = g_scC[i];
            float mn = fmaxf(m, mc);
            s = s*__expf(m - mn) + sc*__expf(mc - mn);
            m = mn;
            ga += g_gsum[i];
        }
        misc[0] = m; misc[1] = s; misc[2] = ga;
    }

    // load Q, V, K tiles (convert to tf32)
    for (int idx = tid*4; idx < CH*hd; idx += 1024) {
        int i = idx >> 5, d = idx & 31;
        float4 q4 = *(const float4*)&g_q[gb + idx];
        float4 v4 = *(const float4*)&g_v[gb + idx];
        float4 k4 = *(const float4*)&g_k[gb + idx];
        float* qd = &Qs[i*40 + d]; float* vd = &Vs[i*40 + d]; float* kd = &Ks[i*40 + d];
        qd[0]=tf32r(q4.x); qd[1]=tf32r(q4.y); qd[2]=tf32r(q4.z); qd[3]=tf32r(q4.w);
        vd[0]=tf32r(v4.x); vd[1]=tf32r(v4.y); vd[2]=tf32r(v4.z); vd[3]=tf32r(v4.w);
        kd[0]=tf32r(k4.x); kd[1]=tf32r(k4.y); kd[2]=tf32r(k4.z); kd[3]=tf32r(k4.w);
    }
    if (tid < CH) {
        float sv = g_sim [bh*Lq + c*CH + tid];
        float gv = g_gate[bh*Lq + c*CH + tid];
        mA[tid] = sv; simA[tid] = sv; sA[tid] = 1.f; gA[tid] = gv; rawg[tid] = gv;
    }
    __syncthreads();

    // Hillis-Steele inclusive scans within chunk
    for (int off = 1; off < CH; off <<= 1) {
        float m2 = 0.f, s2 = 0.f, g2 = 0.f;
        bool act = (tid < CH) && (tid >= off);
        if (act) { m2 = mA[tid-off]; s2 = sA[tid-off]; g2 = gA[tid-off]; }
        __syncthreads();
        if (act) {
            float mn = fmaxf(mA[tid], m2);
            sA[tid] = sA[tid]*__expf(mA[tid] - mn) + s2*__expf(m2 - mn);
            mA[tid] = mn;
            gA[tid] += g2;
        }
        __syncthreads();
    }
    if (tid < CH) {
        float mp = misc[0], sp = misc[1], gp = misc[2];
        float mn = fmaxf(mp, mA[tid]);
        float st = sp*__expf(mp - mn) + sA[tid]*__expf(mA[tid] - mn);
        float sw = __expf(simA[tid] - mn) / (st + EPSf);
        ws[tid]   = 1.f + sw / (1.f + __expf(-sw));
        dinv[tid] = 1.f / (gp + gA[tid] + EPSf);
    }
    __syncthreads();

    // ---- tensor-core phase: each warp owns rows [16w, 16w+16) ----
    const int warp = tid >> 5, lane = tid & 31;
    const int r0 = warp * 16;
    float* myPan = &Pan[r0*40];

    wmma::fragment<wmma::accumulator, 16, 16, 8, float> cY[2];
    // Y2 = Q @ S_prev
    {
        wmma::fill_fragment(cY[0], 0.0f);
        wmma::fill_fragment(cY[1], 0.0f);
        #pragma unroll
        for (int kk = 0; kk < 4; kk++) {
            wmma::fragment<wmma::matrix_a, 16, 16, 8, wmma::precision::tf32, wmma::row_major> a;
            wmma::load_matrix_sync(a, &Qs[r0*40 + kk*8], 40);
            #pragma unroll
            for (int jn = 0; jn < 2; jn++) {
                wmma::fragment<wmma::matrix_b, 16, 16, 8, wmma::precision::tf32, wmma::row_major> bm;
                wmma::load_matrix_sync(bm, &Sps[(kk*8)*40 + jn*16], 40);
                wmma::mma_sync(cY[jn], a, bm, cY[jn]);
            }
        }
    }
    // panels of i: [32j, 32j+32)
    for (int j = 0; j * 32 <= r0 + 15; j++) {
        wmma::fragment<wmma::accumulator, 16, 16, 8, float> cP[2];
        wmma::fill_fragment(cP[0], 0.0f);
        wmma::fill_fragment(cP[1], 0.0f);
        #pragma unroll
        for (int kk = 0; kk < 4; kk++) {
            wmma::fragment<wmma::matrix_a, 16, 16, 8, wmma::precision::tf32, wmma::row_major> a;
            wmma::load_matrix_sync(a, &Qs[r0*40 + kk*8], 40);
            #pragma unroll
            for (int jn = 0; jn < 2; jn++) {
                wmma::fragment<wmma::matrix_b, 16, 16, 8, wmma::precision::tf32, wmma::col_major> bm;
                wmma::load_matrix_sync(bm, &Vs[(j*32 + jn*16)*40 + kk*8], 40);
                wmma::mma_sync(cP[jn], a, bm, cP[jn]);
            }
        }
        wmma::store_matrix_sync(&myPan[0],  cP[0], 40, wmma::mem_row_major);
        wmma::store_matrix_sync(&myPan[16], cP[1], 40, wmma::mem_row_major);
        __syncwarp();
        #pragma unroll
        for (int e = 0; e < 16; e++) {
            int idx = lane + e*32;
            int rr = idx >> 5, ii = idx & 31;
            int rgl = r0 + rr, igl = j*32 + ii;
            float val = myPan[rr*40 + ii];
            val = (igl <= rgl) ? rawg[igl] * val : 0.f;
            myPan[rr*40 + ii] = tf32r(val);
        }
        __syncwarp();
        #pragma unroll
        for (int kk = 0; kk < 4; kk++) {
            wmma::fragment<wmma::matrix_a, 16, 16, 8, wmma::precision::tf32, wmma::row_major> a;
            wmma::load_matrix_sync(a, &myPan[kk*8], 40);
            #pragma unroll
            for (int jn = 0; jn < 2; jn++) {
                wmma::fragment<wmma::matrix_b, 16, 16, 8, wmma::precision::tf32, wmma::row_major> bm;
                wmma::load_matrix_sync(bm, &Ks[(j*32 + kk*8)*40 + jn*16], 40);
                wmma::mma_sync(cY[jn], a, bm, cY[jn]);
            }
        }
        __syncwarp();
    }
    wmma::store_matrix_sync(&myPan[0],  cY[0], 40, wmma::mem_row_major);
    wmma::store_matrix_sync(&myPan[16], cY[1], 40, wmma::mem_row_major);
    __syncwarp();
    #pragma unroll
    for (int rr = 0; rr < 16; rr++) {
        int r = r0 + rr;
        float y = myPan[rr*40 + lane] * ws[r] * dinv[r];
        g_ctx[(b*Lq + c*CH + r)*Dm + h*hd + lane] = y;
    }
}

// ============================================================
// K4: output projection, split-fp16 HMMA. out = ctx @ wo^T + bo
// BM=128, BN=64, grid (32,4).
// ============================================================
__global__ void k_out(const float* __restrict__ wo, const float* __restrict__ bo,
                      float* __restrict__ out)
{
    __shared__ __align__(16) unsigned char smraw[32768];
    __half* Ah = (__half*)smraw;
    __half* Al = Ah + 128*LDH;
    __half* Bh = Al + 128*LDH;
    __half* Bl = Bh + 64*LDH;
    float*  Cs = (float*)smraw;

    const int t  = threadIdx.x;
    const int m0 = blockIdx.x * 128;
    const int n0 = blockIdx.y * 64;
    const int warp = t >> 5;
    const int wm = warp >> 1, wn = warp & 1;

    wmma::fragment<wmma::accumulator, 16, 16, 16, float> c[2][2];
    #pragma unroll
    for (int i = 0; i < 2; i++)
        #pragma unroll
        for (int j = 0; j < 2; j++) wmma::fill_fragment(c[i][j], 0.0f);

    for (int k0 = 0; k0 < 256; k0 += 32) {
        #pragma unroll
        for (int p = 0; p < 4; p++) {
            int f = t + p*256;
            int row = f >> 3, cc = (f & 7) * 4;
            float4 a4 = *(const float4*)(g_ctx + (m0 + row)*256 + k0 + cc);
            int off = row*LDH + cc;
            h_split(a4.x, &Ah[off+0], &Al[off+0]);
            h_split(a4.y, &Ah[off+1], &Al[off+1]);
            h_split(a4.z, &Ah[off+2], &Al[off+2]);
            h_split(a4.w, &Ah[off+3], &Al[off+3]);
        }
        #pragma unroll
        for (int p = 0; p < 2; p++) {
            int f = t + p*256;
            int row = f >> 3, cc = (f & 7) * 4;
            float4 b4 = *(const float4*)(wo + (n0 + row)*256 + k0 + cc);
            int off = row*LDH + cc;
            h_split(b4.x, &Bh[off+0], &Bl[off+0]);
            h_split(b4.y, &Bh[off+1], &Bl[off+1]);
            h_split(b4.z, &Bh[off+2], &Bl[off+2]);
            h_split(b4.w, &Bh[off+3], &Bl[off+3]);
        }
        __syncthreads();
        #pragma unroll
        for (int kk = 0; kk < 2; kk++) {
            wmma::fragment<wmma::matrix_a, 16, 16, 16, __half, wmma::row_major> ah[2], al[2];
            wmma::fragment<wmma::matrix_b, 16, 16, 16, __half, wmma::col_major> bhf[2], blf[2];
            #pragma unroll
            for (int i = 0; i < 2; i++) {
                wmma::load_matrix_sync(ah[i], &Ah[(wm*32 + i*16)*LDH + kk*16], LDH);
                wmma::load_matrix_sync(al[i], &Al[(wm*32 + i*16)*LDH + kk*16], LDH);
            }
            #pragma unroll
            for (int j = 0; j < 2; j++) {
                wmma::load_matrix_sync(bhf[j], &Bh[(wn*32 + j*16)*LDH + kk*16], LDH);
                wmma::load_matrix_sync(blf[j], &Bl[(wn*32 + j*16)*LDH + kk*16], LDH);
            }
            #pragma unroll
            for (int i = 0; i < 2; i++)
                #pragma unroll
                for (int j = 0; j < 2; j++) {
                    wmma::mma_sync(c[i][j], ah[i], bhf[j], c[i][j]);
                    wmma::mma_sync(c[i][j], al[i], bhf[j], c[i][j]);
                    wmma::mma_sync(c[i][j], ah[i], blf[j], c[i][j]);
                }
        }
        __syncthreads();
    }
    #pragma unroll
    for (int i = 0; i < 2; i++)
        #pragma unroll
        for (int j = 0; j < 2; j++)
            wmma::store_matrix_sync(&Cs[(wm*32 + i*16)*64 + wn*32 + j*16], c[i][j], 64, wmma::mem_row_major);
    __syncthreads();
    for (int idx = t; idx < 128*64; idx += 256) {
        int row = idx >> 6, col = idx & 63;
        int o = n0 + col;
        out[(m0 + row)*256 + o] = Cs[idx] + bo[o];
    }
}

// ============================================================
extern "C" void kernel_launch(void* const* d_in, const int* in_sizes, int n_in,
                              void* d_out, int out_size)
{
    const float* x   = (const float*)d_in[0];
    const float* wq  = (const float*)d_in[1];
    const float* bq  = (const float*)d_in[2];
    const float* wk  = (const float*)d_in[3];
    const float* bk  = (const float*)d_in[4];
    const float* wv  = (const float*)d_in[5];
    const float* bv  = (const float*)d_in[6];
    const float* wo  = (const float*)d_in[7];
    const float* bo  = (const float*)d_in[8];
    const float* wg  = (const float*)d_in[9];
    const float* wgb = (const float*)d_in[10];
    const float* kvs = (const float*)d_in[11];
    const float* qks = (const float*)d_in[12];
    float* out = (float*)d_out;

    cudaFuncSetAttribute(k_intra, cudaFuncAttributeMaxDynamicSharedMemorySize, SMEM_INTRA);

    k_qkv      <<<dim3(32, 12), 256>>>(x, wq, bq, wk, bk, wv, bv);
    k_prepchunk<<<256, 256>>>(wg, wgb, kvs, qks);
    k_intra    <<<256, 256, SMEM_INTRA>>>();
    k_out      <<<dim3(32, 4), 256>>>(wo, bo, out);
}

// round 9
// speedup vs baseline: 2.2035x; 1.0294x over previous
#include <cuda_runtime.h>
#include <cuda_fp16.h>
#include <mma.h>
#include <math.h>

using namespace nvcuda;

#define Bsz 2
#define Lq  2048
#define Dm  256
#define Hh  8
#define hd  32
#define CH  128
#define NCH 16
#define BHn (Bsz*Hh)
#define EPSf 1e-5f

// ---- scratch (device globals; no allocations allowed) ----
__device__ float g_q[BHn*Lq*hd];
__device__ float g_k[BHn*Lq*hd];
__device__ float g_v[BHn*Lq*hd];
__device__ float g_sim[BHn*Lq];
__device__ float g_gate[BHn*Lq];
__device__ float g_Sc[BHn*NCH*hd*hd];
__device__ float g_gsum[BHn*NCH];
__device__ float g_mc[BHn*NCH];
__device__ float g_scC[BHn*NCH];
// pre-split fp16 hi/lo operands
__device__ __half d_xh[Bsz*Lq*Dm], d_xl[Bsz*Lq*Dm];       // x
__device__ __half d_wh[4*Dm*Dm],   d_wl[4*Dm*Dm];         // wq,wk,wv,wo
__device__ __half d_ch[Bsz*Lq*Dm], d_cl[Bsz*Lq*Dm];       // ctx

__device__ __forceinline__ float warpSum(float v) {
    #pragma unroll
    for (int o = 16; o; o >>= 1) v += __shfl_xor_sync(0xffffffffu, v, o);
    return v;
}
__device__ __forceinline__ float tf32r(float f) { return wmma::__float_to_tf32(f); }

__device__ __forceinline__ void cpa16(unsigned sa, const void* g) {
    asm volatile("cp.async.ca.shared.global [%0], [%1], 16;" :: "r"(sa), "l"(g));
}
#define CP_COMMIT()  asm volatile("cp.async.commit_group;")
#define CP_WAIT(n)   asm volatile("cp.async.wait_group %0;" :: "n"(n))

// ============================================================
// K0: split x and the four weight matrices into fp16 hi/lo.
// 327680 float4s total: 262144 (x) + 4*16384 (w). grid 1280x256.
// ============================================================
__global__ void k_split(const float* __restrict__ x,
                        const float* __restrict__ wq, const float* __restrict__ wk,
                        const float* __restrict__ wv, const float* __restrict__ wo)
{
    int i = blockIdx.x*256 + threadIdx.x;
    const float4* src;
    __half *dh, *dl;
    if (i < 262144) {
        src = (const float4*)x + i;                         // FIXED: offset by i
        dh = d_xh + i*4; dl = d_xl + i*4;
    } else {
        int j = i - 262144;
        int w = j >> 14, off = j & 16383;
        const float* ws = (w==0)?wq:((w==1)?wk:((w==2)?wv:wo));
        src = (const float4*)ws + off;
        dh = d_wh + w*65536 + off*4; dl = d_wl + w*65536 + off*4;
    }
    float4 f = *src;
    __half h0=__float2half_rn(f.x), h1=__float2half_rn(f.y),
           h2=__float2half_rn(f.z), h3=__float2half_rn(f.w);
    ((__half2*)dh)[0] = __halves2half2(h0, h1);
    ((__half2*)dh)[1] = __halves2half2(h2, h3);
    ((__half2*)dl)[0] = __halves2half2(__float2half_rn(f.x-__half2float(h0)),
                                       __float2half_rn(f.y-__half2float(h1)));
    ((__half2*)dl)[1] = __halves2half2(__float2half_rn(f.z-__half2float(h2)),
                                       __float2half_rn(f.w-__half2float(h3)));
}

// ============================================================
// K1: QKV projection, pre-split fp16, cp.async 2-stage pipeline.
// BM=128, BN=64, BK=32. 256 threads = 8 warps (4m x 2n), warp 32x32.
// grid (32, 12). dyn smem: 2 stages x 30720B. Stage layout (bytes):
//   Ah@0 (128x40h) Al@10240 Bh@20480 (64x40h) Bl@25600
// ============================================================
#define STG1 30720
__global__ void k_qkv(const float* __restrict__ bq, const float* __restrict__ bk,
                      const float* __restrict__ bv)
{
    extern __shared__ __align__(16) unsigned char smraw[];
    const unsigned sbase = (unsigned)__cvta_generic_to_shared(smraw);
    const int t   = threadIdx.x;
    const int m0  = blockIdx.x * 128;
    const int mat = blockIdx.y >> 2;
    const int n0  = (blockIdx.y & 3) * 64;
    const __half* Bgh = d_wh + mat*65536;
    const __half* Bgl = d_wl + mat*65536;
    const float* bias = (mat == 0) ? bq : ((mat == 1) ? bk : bv);
    const int warp = t >> 5;
    const int wm = warp >> 1, wn = warp & 1;

    wmma::fragment<wmma::accumulator, 16, 16, 16, float> c[2][2];
    #pragma unroll
    for (int i = 0; i < 2; i++)
        #pragma unroll
        for (int j = 0; j < 2; j++) wmma::fill_fragment(c[i][j], 0.0f);

    auto issue = [&](int s, int k0) {
        unsigned sb = sbase + s*STG1;
        #pragma unroll
        for (int p = 0; p < 2; p++) {
            int slot = t + p*256;
            int row = slot >> 2, seg = slot & 3;
            int go = (m0 + row)*256 + k0 + seg*8;
            unsigned so = row*80 + seg*16;
            cpa16(sb + so,         d_xh + go);
            cpa16(sb + 10240 + so, d_xl + go);
        }
        {
            int row = t >> 2, seg = t & 3;
            int go = (n0 + row)*256 + k0 + seg*8;
            unsigned so = row*80 + seg*16;
            cpa16(sb + 20480 + so, Bgh + go);
            cpa16(sb + 25600 + so, Bgl + go);
        }
    };

    issue(0, 0); CP_COMMIT();
    int buf = 0;
    for (int it = 0; it < 8; it++) {
        if (it < 7) { issue(buf^1, (it+1)*32); CP_COMMIT(); CP_WAIT(1); }
        else        { CP_WAIT(0); }
        __syncthreads();
        const __half* Ah = (const __half*)(smraw + buf*STG1);
        const __half* Al = Ah + 5120;
        const __half* Bh = Ah + 10240;
        const __half* Bl = Ah + 12800;
        #pragma unroll
        for (int kk = 0; kk < 2; kk++) {
            wmma::fragment<wmma::matrix_a, 16, 16, 16, __half, wmma::row_major> ah[2], al[2];
            wmma::fragment<wmma::matrix_b, 16, 16, 16, __half, wmma::col_major> bh[2], bl[2];
            #pragma unroll
            for (int i = 0; i < 2; i++) {
                wmma::load_matrix_sync(ah[i], Ah + (wm*32 + i*16)*40 + kk*16, 40);
                wmma::load_matrix_sync(al[i], Al + (wm*32 + i*16)*40 + kk*16, 40);
            }
            #pragma unroll
            for (int j = 0; j < 2; j++) {
                wmma::load_matrix_sync(bh[j], Bh + (wn*32 + j*16)*40 + kk*16, 40);
                wmma::load_matrix_sync(bl[j], Bl + (wn*32 + j*16)*40 + kk*16, 40);
            }
            #pragma unroll
            for (int i = 0; i < 2; i++)
                #pragma unroll
                for (int j = 0; j < 2; j++) {
                    wmma::mma_sync(c[i][j], ah[i], bh[j], c[i][j]);
                    wmma::mma_sync(c[i][j], al[i], bh[j], c[i][j]);
                    wmma::mma_sync(c[i][j], ah[i], bl[j], c[i][j]);
                }
        }
        __syncthreads();
        buf ^= 1;
    }
    float* Cs = (float*)smraw;                    // 128x64 fp32 = 32KB
    #pragma unroll
    for (int i = 0; i < 2; i++)
        #pragma unroll
        for (int j = 0; j < 2; j++)
            wmma::store_matrix_sync(&Cs[(wm*32 + i*16)*64 + wn*32 + j*16], c[i][j], 64, wmma::mem_row_major);
    __syncthreads();
    float* dst = (mat == 0) ? g_q : ((mat == 1) ? g_k : g_v);
    for (int idx = t; idx < 128*64; idx += 256) {
        int row = idx >> 6, col = idx & 63;
        int m = m0 + row;
        int b = m >> 11, l = m & 2047;
        int o = n0 + col;
        int hidx = o >> 5, d = o & 31;
        dst[((b*Hh + hidx)*Lq + l)*hd + d] = Cs[idx] + bias[o];
    }
}

// ============================================================
// K2: fused per-position preprocess + per-chunk sums (fp32).
// grid: BHn*NCH = 256 blocks, 256 threads.
// ============================================================
__global__ void k_prepchunk(const float* __restrict__ wg, const float* __restrict__ wgb,
                            const float* __restrict__ kvs, const float* __restrict__ qks)
{
    __shared__ float Ks[CH*hd];
    __shared__ float Vs[CH*hd];
    __shared__ float Ms[32*33];
    __shared__ float gs[CH], sims[CH];
    const int tid = threadIdx.x;
    const int bx  = blockIdx.x;
    const int bh  = bx >> 4, c = bx & 15;
    const int h   = bh & 7;
    for (int idx = tid; idx < 1024; idx += 256) {
        int d = idx >> 5, e = idx & 31;
        Ms[d*33 + e] = kvs[h*1024 + idx] * wg[idx];
    }
    __syncthreads();
    const float qscale = qks[h];
    const float wb0    = wgb[0];
    const int warp = tid >> 5, lane = tid & 31;
    for (int jj = 0; jj < 16; jj++) {
        int pos  = warp*16 + jj;
        int l    = c*CH + pos;
        int base = (bh*Lq + l)*hd + lane;
        float qd = g_q[base], kd = g_k[base], vd = g_v[base];
        float sim = warpSum(qd*kd) * qscale;
        float kh  = kd / fmaxf(sqrtf(warpSum(kd*kd)), 1e-12f);
        float vh  = vd / fmaxf(sqrtf(warpSum(vd*vd)), 1e-12f);
        Ks[pos*hd + lane] = kh;
        Vs[pos*hd + lane] = vh;
        g_k[base] = kh;
        g_v[base] = vh;
        __syncwarp();
        float td = 0.f;
        #pragma unroll
        for (int e = 0; e < 32; e++)
            td += Ms[lane*33 + e] * Ks[pos*hd + e];
        float logit = warpSum(vh*td) + wb0;
        float r = fmaxf(logit, 0.f);
        float gate = r*r + EPSf;
        if (lane == 0) {
            gs[pos] = gate; sims[pos] = sim;
            g_gate[bh*Lq + l] = gate; g_sim[bh*Lq + l] = sim;
        }
    }
    __syncthreads();
    const int d = tid >> 3, e0 = (tid & 7) * 4;
    float4 acc = {0.f, 0.f, 0.f, 0.f};
    for (int i = 0; i < CH; i++) {
        float cfv = gs[i] * Vs[i*hd + d];
        float4 k4 = *(float4*)&Ks[i*hd + e0];
        acc.x += cfv*k4.x; acc.y += cfv*k4.y; acc.z += cfv*k4.z; acc.w += cfv*k4.w;
    }
    *(float4*)&g_Sc[bx*1024 + tid*4] = acc;
    if (tid < 32) {
        float m = -1e30f;
        #pragma unroll
        for (int k = 0; k < 4; k++) m = fmaxf(m, sims[tid + 32*k]);
        #pragma unroll
        for (int o = 16; o; o >>= 1) m = fmaxf(m, __shfl_xor_sync(0xffffffffu, m, o));
        float s = 0.f, gsum = 0.f;
        #pragma unroll
        for (int k = 0; k < 4; k++) { s += __expf(sims[tid + 32*k] - m); gsum += gs[tid + 32*k]; }
        s = warpSum(s); gsum = warpSum(gsum);
        if (tid == 0) { g_mc[bx] = m; g_scC[bx] = s; g_gsum[bx] = gsum; }
    }
}

// ============================================================
// K3: intra-chunk via tf32 tensor cores + scalar scans.
// grid BHn*NCH = 256 blocks, 256 threads (8 warps).
// Epilogue writes ctx as fp16 hi/lo for k_out.
// ============================================================
#define QS_O   0
#define VS_O   5120
#define KS_O   10240
#define PAN_O  15360
#define SPS_O  20480
#define SCN_O  21760
#define MSC_O  (SCN_O + 7*128)
#define SMEM_INTRA ((MSC_O + 4) * 4)

__global__ void k_intra()
{
    extern __shared__ float sm[];
    float* Qs   = sm + QS_O;
    float* Vs   = sm + VS_O;
    float* Ks   = sm + KS_O;
    float* Pan  = sm + PAN_O;
    float* Sps  = sm + SPS_O;
    float* mA   = sm + SCN_O;
    float* sA   = mA + 128;
    float* gA   = sA + 128;
    float* simA = gA + 128;
    float* rawg = simA + 128;
    float* ws   = rawg + 128;
    float* dinv = ws + 128;
    float* misc = sm + MSC_O;

    const int tid = threadIdx.x;
    const int bx  = blockIdx.x;
    const int bh  = bx >> 4, c = bx & 15;
    const int b   = bh >> 3, h = bh & 7;
    const int gb  = (bh*Lq + c*CH)*hd;

    {
        int idx = tid*4;
        float4 a = {0.f, 0.f, 0.f, 0.f};
        for (int cc = 0; cc < c; cc++) {
            float4 v = *(const float4*)&g_Sc[(bh*NCH + cc)*1024 + idx];
            a.x += v.x; a.y += v.y; a.z += v.z; a.w += v.w;
        }
        int d = idx >> 5, e0 = idx & 31;
        Sps[d*40 + e0 + 0] = tf32r(a.x);
        Sps[d*40 + e0 + 1] = tf32r(a.y);
        Sps[d*40 + e0 + 2] = tf32r(a.z);
        Sps[d*40 + e0 + 3] = tf32r(a.w);
    }
    if (tid == 0) {
        float m = -1e30f, s = 0.f, ga = 0.f;
        for (int cc = 0; cc < c; cc++) {
            int i = bh*NCH + cc;
            float mc = g_mc[i], sc = g_scC[i];
            float mn = fmaxf(m, mc);
            s = s*__expf(m - mn) + sc*__expf(mc - mn);
            m = mn;
            ga += g_gsum[i];
        }
        misc[0] = m; misc[1] = s; misc[2] = ga;
    }

    for (int idx = tid*4; idx < CH*hd; idx += 1024) {
        int i = idx >> 5, d = idx & 31;
        float4 q4 = *(const float4*)&g_q[gb + idx];
        float4 v4 = *(const float4*)&g_v[gb + idx];
        float4 k4 = *(const float4*)&g_k[gb + idx];
        float* qd = &Qs[i*40 + d]; float* vd = &Vs[i*40 + d]; float* kd = &Ks[i*40 + d];
        qd[0]=tf32r(q4.x); qd[1]=tf32r(q4.y); qd[2]=tf32r(q4.z); qd[3]=tf32r(q4.w);
        vd[0]=tf32r(v4.x); vd[1]=tf32r(v4.y); vd[2]=tf32r(v4.z); vd[3]=tf32r(v4.w);
        kd[0]=tf32r(k4.x); kd[1]=tf32r(k4.y); kd[2]=tf32r(k4.z); kd[3]=tf32r(k4.w);
    }
    if (tid < CH) {
        float sv = g_sim [bh*Lq + c*CH + tid];
        float gv = g_gate[bh*Lq + c*CH + tid];
        mA[tid] = sv; simA[tid] = sv; sA[tid] = 1.f; gA[tid] = gv; rawg[tid] = gv;
    }
    __syncthreads();

    for (int off = 1; off < CH; off <<= 1) {
        float m2 = 0.f, s2 = 0.f, g2 = 0.f;
        bool act = (tid < CH) && (tid >= off);
        if (act) { m2 = mA[tid-off]; s2 = sA[tid-off]; g2 = gA[tid-off]; }
        __syncthreads();
        if (act) {
            float mn = fmaxf(mA[tid], m2);
            sA[tid] = sA[tid]*__expf(mA[tid] - mn) + s2*__expf(m2 - mn);
            mA[tid] = mn;
            gA[tid] += g2;
        }
        __syncthreads();
    }
    if (tid < CH) {
        float mp = misc[0], sp = misc[1], gp = misc[2];
        float mn = fmaxf(mp, mA[tid]);
        float st = sp*__expf(mp - mn) + sA[tid]*__expf(mA[tid] - mn);
        float sw = __expf(simA[tid] - mn) / (st + EPSf);
        ws[tid]   = 1.f + sw / (1.f + __expf(-sw));
        dinv[tid] = 1.f / (gp + gA[tid] + EPSf);
    }
    __syncthreads();

    const int warp = tid >> 5, lane = tid & 31;
    const int r0 = warp * 16;
    float* myPan = &Pan[r0*40];

    wmma::fragment<wmma::accumulator, 16, 16, 8, float> cY[2];
    {
        wmma::fill_fragment(cY[0], 0.0f);
        wmma::fill_fragment(cY[1], 0.0f);
        #pragma unroll
        for (int kk = 0; kk < 4; kk++) {
            wmma::fragment<wmma::matrix_a, 16, 16, 8, wmma::precision::tf32, wmma::row_major> a;
            wmma::load_matrix_sync(a, &Qs[r0*40 + kk*8], 40);
            #pragma unroll
            for (int jn = 0; jn < 2; jn++) {
                wmma::fragment<wmma::matrix_b, 16, 16, 8, wmma::precision::tf32, wmma::row_major> bm;
                wmma::load_matrix_sync(bm, &Sps[(kk*8)*40 + jn*16], 40);
                wmma::mma_sync(cY[jn], a, bm, cY[jn]);
            }
        }
    }
    for (int j = 0; j * 32 <= r0 + 15; j++) {
        wmma::fragment<wmma::accumulator, 16, 16, 8, float> cP[2];
        wmma::fill_fragment(cP[0], 0.0f);
        wmma::fill_fragment(cP[1], 0.0f);
        #pragma unroll
        for (int kk = 0; kk < 4; kk++) {
            wmma::fragment<wmma::matrix_a, 16, 16, 8, wmma::precision::tf32, wmma::row_major> a;
            wmma::load_matrix_sync(a, &Qs[r0*40 + kk*8], 40);
            #pragma unroll
            for (int jn = 0; jn < 2; jn++) {
                wmma::fragment<wmma::matrix_b, 16, 16, 8, wmma::precision::tf32, wmma::col_major> bm;
                wmma::load_matrix_sync(bm, &Vs[(j*32 + jn*16)*40 + kk*8], 40);
                wmma::mma_sync(cP[jn], a, bm, cP[jn]);
            }
        }
        wmma::store_matrix_sync(&myPan[0],  cP[0], 40, wmma::mem_row_major);
        wmma::store_matrix_sync(&myPan[16], cP[1], 40, wmma::mem_row_major);
        __syncwarp();
        #pragma unroll
        for (int e = 0; e < 16; e++) {
            int idx = lane + e*32;
            int rr = idx >> 5, ii = idx & 31;
            int rgl = r0 + rr, igl = j*32 + ii;
            float val = myPan[rr*40 + ii];
            val = (igl <= rgl) ? rawg[igl] * val : 0.f;
            myPan[rr*40 + ii] = tf32r(val);
        }
        __syncwarp();
        #pragma unroll
        for (int kk = 0; kk < 4; kk++) {
            wmma::fragment<wmma::matrix_a, 16, 16, 8, wmma::precision::tf32, wmma::row_major> a;
            wmma::load_matrix_sync(a, &myPan[kk*8], 40);
            #pragma unroll
            for (int jn = 0; jn < 2; jn++) {
                wmma::fragment<wmma::matrix_b, 16, 16, 8, wmma::precision::tf32, wmma::row_major> bm;
                wmma::load_matrix_sync(bm, &Ks[(j*32 + kk*8)*40 + jn*16], 40);
                wmma::mma_sync(cY[jn], a, bm, cY[jn]);
            }
        }
        __syncwarp();
    }
    wmma::store_matrix_sync(&myPan[0],  cY[0], 40, wmma::mem_row_major);
    wmma::store_matrix_sync(&myPan[16], cY[1], 40, wmma::mem_row_major);
    __syncwarp();
    #pragma unroll
    for (int rr = 0; rr < 16; rr++) {
        int r = r0 + rr;
        float y = myPan[rr*40 + lane] * ws[r] * dinv[r];
        int cidx = (b*Lq + c*CH + r)*Dm + h*hd + lane;
        __half hy = __float2half_rn(y);
        d_ch[cidx] = hy;
        d_cl[cidx] = __float2half_rn(y - __half2float(hy));
    }
}

// ============================================================
// K4: output projection, pre-split fp16 + cp.async. out = ctx @ wo^T + bo
// BM=64, BN=64, grid (64,4). Stage: Ah@0 Al@5120 Bh@10240 Bl@15360 (20480B)
// ============================================================
#define STG2 20480
__global__ void k_out(const float* __restrict__ bo, float* __restrict__ out)
{
    extern __shared__ __align__(16) unsigned char smraw[];
    const unsigned sbase = (unsigned)__cvta_generic_to_shared(smraw);
    const int t  = threadIdx.x;
    const int m0 = blockIdx.x * 64;
    const int n0 = blockIdx.y * 64;
    const __half* Bgh = d_wh + 3*65536;
    const __half* Bgl = d_wl + 3*65536;
    const int warp = t >> 5;
    const int wm = warp >> 1, wn = warp & 1;   // 4x2, warp tile 16x32

    wmma::fragment<wmma::accumulator, 16, 16, 16, float> c[2];
    wmma::fill_fragment(c[0], 0.0f);
    wmma::fill_fragment(c[1], 0.0f);

    auto issue = [&](int s, int k0) {
        unsigned sb = sbase + s*STG2;
        int row = t >> 2, seg = t & 3;
        unsigned so = row*80 + seg*16;
        int ga = (m0 + row)*256 + k0 + seg*8;
        int gbb = (n0 + row)*256 + k0 + seg*8;
        cpa16(sb + so,         d_ch + ga);
        cpa16(sb + 5120 + so,  d_cl + ga);
        cpa16(sb + 10240 + so, Bgh + gbb);
        cpa16(sb + 15360 + so, Bgl + gbb);
    };

    issue(0, 0); CP_COMMIT();
    int buf = 0;
    for (int it = 0; it < 8; it++) {
        if (it < 7) { issue(buf^1, (it+1)*32); CP_COMMIT(); CP_WAIT(1); }
        else        { CP_WAIT(0); }
        __syncthreads();
        const __half* Ah = (const __half*)(smraw + buf*STG2);
        const __half* Al = Ah + 2560;
        const __half* Bh = Ah + 5120;
        const __half* Bl = Ah + 7680;
        #pragma unroll
        for (int kk = 0; kk < 2; kk++) {
            wmma::fragment<wmma::matrix_a, 16, 16, 16, __half, wmma::row_major> ah, al;
            wmma::fragment<wmma::matrix_b, 16, 16, 16, __half, wmma::col_major> bh[2], bl[2];
            wmma::load_matrix_sync(ah, Ah + (wm*16)*40 + kk*16, 40);
            wmma::load_matrix_sync(al, Al + (wm*16)*40 + kk*16, 40);
            #pragma unroll
            for (int j = 0; j < 2; j++) {
                wmma::load_matrix_sync(bh[j], Bh + (wn*32 + j*16)*40 + kk*16, 40);
                wmma::load_matrix_sync(bl[j], Bl + (wn*32 + j*16)*40 + kk*16, 40);
            }
            #pragma unroll
            for (int j = 0; j < 2; j++) {
                wmma::mma_sync(c[j], ah, bh[j], c[j]);
                wmma::mma_sync(c[j], al, bh[j], c[j]);
                wmma::mma_sync(c[j], ah, bl[j], c[j]);
            }
        }
        __syncthreads();
        buf ^= 1;
    }
    float* Cs = (float*)smraw;                 // 64x64 fp32 = 16KB
    #pragma unroll
    for (int j = 0; j < 2; j++)
        wmma::store_matrix_sync(&Cs[(wm*16)*64 + wn*32 + j*16], c[j], 64, wmma::mem_row_major);
    __syncthreads();
    for (int idx = t; idx < 64*64; idx += 256) {
        int row = idx >> 6, col = idx & 63;
        int o = n0 + col;
        out[(m0 + row)*256 + o] = Cs[idx] + bo[o];
    }
}

// ============================================================
extern "C" void kernel_launch(void* const* d_in, const int* in_sizes, int n_in,
                              void* d_out, int out_size)
{
    const float* x   = (const float*)d_in[0];
    const float* wq  = (const float*)d_in[1];
    const float* bq  = (const float*)d_in[2];
    const float* wk  = (const float*)d_in[3];
    const float* bk  = (const float*)d_in[4];
    const float* wv  = (const float*)d_in[5];
    const float* bv  = (const float*)d_in[6];
    const float* wo  = (const float*)d_in[7];
    const float* bo  = (const float*)d_in[8];
    const float* wg  = (const float*)d_in[9];
    const float* wgb = (const float*)d_in[10];
    const float* kvs = (const float*)d_in[11];
    const float* qks = (const float*)d_in[12];
    float* out = (float*)d_out;

    cudaFuncSetAttribute(k_qkv,   cudaFuncAttributeMaxDynamicSharedMemorySize, 2*STG1);
    cudaFuncSetAttribute(k_intra, cudaFuncAttributeMaxDynamicSharedMemorySize, SMEM_INTRA);
    cudaFuncSetAttribute(k_out,   cudaFuncAttributeMaxDynamicSharedMemorySize, 2*STG2);

    k_split    <<<1280, 256>>>(x, wq, wk, wv, wo);
    k_qkv      <<<dim3(32, 12), 256, 2*STG1>>>(bq, bk, bv);
    k_prepchunk<<<256, 256>>>(wg, wgb, kvs, qks);
    k_intra    <<<256, 256, SMEM_INTRA>>>();
    k_out      <<<dim3(64, 4), 256, 2*STG2>>>(bo, out);
}

// round 12
// speedup vs baseline: 2.3911x; 1.0851x over previous
#include <cuda_runtime.h>
#include <cuda_fp16.h>
#include <mma.h>
#include <math.h>

using namespace nvcuda;

#define Bsz 2
#define Lq  2048
#define Dm  256
#define Hh  8
#define hd  32
#define CH  128
#define NCH 16
#define BHn (Bsz*Hh)
#define EPSf 1e-5f

// ---- scratch (device globals; no allocations allowed) ----
__device__ float g_q[BHn*Lq*hd];
__device__ float g_k[BHn*Lq*hd];
__device__ float g_v[BHn*Lq*hd];
__device__ float g_sim[BHn*Lq];
__device__ float g_gate[BHn*Lq];
__device__ float g_Sc[BHn*NCH*hd*hd];
__device__ float g_gsum[BHn*NCH];
__device__ float g_mc[BHn*NCH];
__device__ float g_scC[BHn*NCH];
// pre-split fp16 hi/lo operands
__device__ __half d_xh[Bsz*Lq*Dm], d_xl[Bsz*Lq*Dm];       // x
__device__ __half d_wh[4*Dm*Dm],   d_wl[4*Dm*Dm];         // wq,wk,wv,wo
__device__ __half d_ch[Bsz*Lq*Dm], d_cl[Bsz*Lq*Dm];       // ctx

__device__ __forceinline__ float warpSum(float v) {
    #pragma unroll
    for (int o = 16; o; o >>= 1) v += __shfl_xor_sync(0xffffffffu, v, o);
    return v;
}
__device__ __forceinline__ float tf32r(float f) { return wmma::__float_to_tf32(f); }

__device__ __forceinline__ void cpa16(unsigned sa, const void* g) {
    asm volatile("cp.async.ca.shared.global [%0], [%1], 16;" :: "r"(sa), "l"(g));
}
#define CP_COMMIT()  asm volatile("cp.async.commit_group;")
#define CP_WAIT(n)   asm volatile("cp.async.wait_group %0;" :: "n"(n))

// ============================================================
// K0: split x and the four weight matrices into fp16 hi/lo.
// ============================================================
__global__ void k_split(const float* __restrict__ x,
                        const float* __restrict__ wq, const float* __restrict__ wk,
                        const float* __restrict__ wv, const float* __restrict__ wo)
{
    int i = blockIdx.x*256 + threadIdx.x;
    const float4* src;
    __half *dh, *dl;
    if (i < 262144) {
        src = (const float4*)x + i;
        dh = d_xh + i*4; dl = d_xl + i*4;
    } else {
        int j = i - 262144;
        int w = j >> 14, off = j & 16383;
        const float* ws = (w==0)?wq:((w==1)?wk:((w==2)?wv:wo));
        src = (const float4*)ws + off;
        dh = d_wh + w*65536 + off*4; dl = d_wl + w*65536 + off*4;
    }
    float4 f = *src;
    __half h0=__float2half_rn(f.x), h1=__float2half_rn(f.y),
           h2=__float2half_rn(f.z), h3=__float2half_rn(f.w);
    ((__half2*)dh)[0] = __halves2half2(h0, h1);
    ((__half2*)dh)[1] = __halves2half2(h2, h3);
    ((__half2*)dl)[0] = __halves2half2(__float2half_rn(f.x-__half2float(h0)),
                                       __float2half_rn(f.y-__half2float(h1)));
    ((__half2*)dl)[1] = __halves2half2(__float2half_rn(f.z-__half2float(h2)),
                                       __float2half_rn(f.w-__half2float(h3)));
}

// ============================================================
// K1: QKV projection, pre-split fp16, cp.async 2-stage pipeline.
// ============================================================
#define STG1 30720
__global__ void k_qkv(const float* __restrict__ bq, const float* __restrict__ bk,
                      const float* __restrict__ bv)
{
    extern __shared__ __align__(16) unsigned char smraw[];
    const unsigned sbase = (unsigned)__cvta_generic_to_shared(smraw);
    const int t   = threadIdx.x;
    const int m0  = blockIdx.x * 128;
    const int mat = blockIdx.y >> 2;
    const int n0  = (blockIdx.y & 3) * 64;
    const __half* Bgh = d_wh + mat*65536;
    const __half* Bgl = d_wl + mat*65536;
    const float* bias = (mat == 0) ? bq : ((mat == 1) ? bk : bv);
    const int warp = t >> 5;
    const int wm = warp >> 1, wn = warp & 1;

    wmma::fragment<wmma::accumulator, 16, 16, 16, float> c[2][2];
    #pragma unroll
    for (int i = 0; i < 2; i++)
        #pragma unroll
        for (int j = 0; j < 2; j++) wmma::fill_fragment(c[i][j], 0.0f);

    auto issue = [&](int s, int k0) {
        unsigned sb = sbase + s*STG1;
        #pragma unroll
        for (int p = 0; p < 2; p++) {
            int slot = t + p*256;
            int row = slot >> 2, seg = slot & 3;
            int go = (m0 + row)*256 + k0 + seg*8;
            unsigned so = row*80 + seg*16;
            cpa16(sb + so,         d_xh + go);
            cpa16(sb + 10240 + so, d_xl + go);
        }
        {
            int row = t >> 2, seg = t & 3;
            int go = (n0 + row)*256 + k0 + seg*8;
            unsigned so = row*80 + seg*16;
            cpa16(sb + 20480 + so, Bgh + go);
            cpa16(sb + 25600 + so, Bgl + go);
        }
    };

    issue(0, 0); CP_COMMIT();
    int buf = 0;
    for (int it = 0; it < 8; it++) {
        if (it < 7) { issue(buf^1, (it+1)*32); CP_COMMIT(); CP_WAIT(1); }
        else        { CP_WAIT(0); }
        __syncthreads();
        const __half* Ah = (const __half*)(smraw + buf*STG1);
        const __half* Al = Ah + 5120;
        const __half* Bh = Ah + 10240;
        const __half* Bl = Ah + 12800;
        #pragma unroll
        for (int kk = 0; kk < 2; kk++) {
            wmma::fragment<wmma::matrix_a, 16, 16, 16, __half, wmma::row_major> ah[2], al[2];
            wmma::fragment<wmma::matrix_b, 16, 16, 16, __half, wmma::col_major> bh[2], bl[2];
            #pragma unroll
            for (int i = 0; i < 2; i++) {
                wmma::load_matrix_sync(ah[i], Ah + (wm*32 + i*16)*40 + kk*16, 40);
                wmma::load_matrix_sync(al[i], Al + (wm*32 + i*16)*40 + kk*16, 40);
            }
            #pragma unroll
            for (int j = 0; j < 2; j++) {
                wmma::load_matrix_sync(bh[j], Bh + (wn*32 + j*16)*40 + kk*16, 40);
                wmma::load_matrix_sync(bl[j], Bl + (wn*32 + j*16)*40 + kk*16, 40);
            }
            #pragma unroll
            for (int i = 0; i < 2; i++)
                #pragma unroll
                for (int j = 0; j < 2; j++) {
                    wmma::mma_sync(c[i][j], ah[i], bh[j], c[i][j]);
                    wmma::mma_sync(c[i][j], al[i], bh[j], c[i][j]);
                    wmma::mma_sync(c[i][j], ah[i], bl[j], c[i][j]);
                }
        }
        __syncthreads();
        buf ^= 1;
    }
    float* Cs = (float*)smraw;
    #pragma unroll
    for (int i = 0; i < 2; i++)
        #pragma unroll
        for (int j = 0; j < 2; j++)
            wmma::store_matrix_sync(&Cs[(wm*32 + i*16)*64 + wn*32 + j*16], c[i][j], 64, wmma::mem_row_major);
    __syncthreads();
    float* dst = (mat == 0) ? g_q : ((mat == 1) ? g_k : g_v);
    for (int idx = t; idx < 128*64; idx += 256) {
        int row = idx >> 6, col = idx & 63;
        int m = m0 + row;
        int b = m >> 11, l = m & 2047;
        int o = n0 + col;
        int hidx = o >> 5, d = o & 31;
        dst[((b*Hh + hidx)*Lq + l)*hd + d] = Cs[idx] + bias[o];
    }
}

// ============================================================
// K2: fused per-position preprocess + per-chunk sums (fp32).
// ============================================================
__global__ void k_prepchunk(const float* __restrict__ wg, const float* __restrict__ wgb,
                            const float* __restrict__ kvs, const float* __restrict__ qks)
{
    __shared__ float Ks[CH*hd];
    __shared__ float Vs[CH*hd];
    __shared__ float Ms[32*33];
    __shared__ float gs[CH], sims[CH];
    const int tid = threadIdx.x;
    const int bx  = blockIdx.x;
    const int bh  = bx >> 4, c = bx & 15;
    const int h   = bh & 7;
    for (int idx = tid; idx < 1024; idx += 256) {
        int d = idx >> 5, e = idx & 31;
        Ms[d*33 + e] = kvs[h*1024 + idx] * wg[idx];
    }
    __syncthreads();
    const float qscale = qks[h];
    const float wb0    = wgb[0];
    const int warp = tid >> 5, lane = tid & 31;
    for (int jj = 0; jj < 16; jj++) {
        int pos  = warp*16 + jj;
        int l    = c*CH + pos;
        int base = (bh*Lq + l)*hd + lane;
        float qd = g_q[base], kd = g_k[base], vd = g_v[base];
        float sim = warpSum(qd*kd) * qscale;
        float kh  = kd / fmaxf(sqrtf(warpSum(kd*kd)), 1e-12f);
        float vh  = vd / fmaxf(sqrtf(warpSum(vd*vd)), 1e-12f);
        Ks[pos*hd + lane] = kh;
        Vs[pos*hd + lane] = vh;
        g_k[base] = kh;
        g_v[base] = vh;
        __syncwarp();
        float td = 0.f;
        #pragma unroll
        for (int e = 0; e < 32; e++)
            td += Ms[lane*33 + e] * Ks[pos*hd + e];
        float logit = warpSum(vh*td) + wb0;
        float r = fmaxf(logit, 0.f);
        float gate = r*r + EPSf;
        if (lane == 0) {
            gs[pos] = gate; sims[pos] = sim;
            g_gate[bh*Lq + l] = gate; g_sim[bh*Lq + l] = sim;
        }
    }
    __syncthreads();
    const int d = tid >> 3, e0 = (tid & 7) * 4;
    float4 acc = {0.f, 0.f, 0.f, 0.f};
    for (int i = 0; i < CH; i++) {
        float cfv = gs[i] * Vs[i*hd + d];
        float4 k4 = *(float4*)&Ks[i*hd + e0];
        acc.x += cfv*k4.x; acc.y += cfv*k4.y; acc.z += cfv*k4.z; acc.w += cfv*k4.w;
    }
    *(float4*)&g_Sc[bx*1024 + tid*4] = acc;
    if (tid < 32) {
        float m = -1e30f;
        #pragma unroll
        for (int k = 0; k < 4; k++) m = fmaxf(m, sims[tid + 32*k]);
        #pragma unroll
        for (int o = 16; o; o >>= 1) m = fmaxf(m, __shfl_xor_sync(0xffffffffu, m, o));
        float s = 0.f, gsum = 0.f;
        #pragma unroll
        for (int k = 0; k < 4; k++) { s += __expf(sims[tid + 32*k] - m); gsum += gs[tid + 32*k]; }
        s = warpSum(s); gsum = warpSum(gsum);
        if (tid == 0) { g_mc[bx] = m; g_scC[bx] = s; g_gsum[bx] = gsum; }
    }
}

// ============================================================
// K3: intra-chunk, restructured:
//  - warp-shfl scans (2 barriers instead of 14)
//  - gate folded into V (Vg), sub-chunk (32) state decomposition:
//      Ssub_j = Vg_j^T @ K_j  (j=0..2, TC, shared)
//      SP_sb  = Sps + sum_{j<sb} Ssub_j
//      warp w (rows 16w..16w+15, sb=w/2):
//        Y = Q@SP_sb + mask(Q@Vg_sb^T) @ K_sb      (one masked panel)
// ============================================================
#define QS_O   0
#define VG_O   5120
#define KS_O   10240
#define SP_O   15360
#define PAN_O  20480
#define RAWG_O 25600
#define SIMA_O 25728
#define WS_O   25856
#define DINV_O 25984
#define AGG_O  26112
#define MSC_O  26124
#define SMEM_INTRA ((MSC_O + 4) * 4)

__global__ void k_intra()
{
    extern __shared__ float sm[];
    float* Qs   = sm + QS_O;
    float* Vg   = sm + VG_O;
    float* Ks   = sm + KS_O;
    float* SP   = sm + SP_O;
    float* Pan  = sm + PAN_O;
    float* rawg = sm + RAWG_O;
    float* simA = sm + SIMA_O;
    float* ws   = sm + WS_O;
    float* dinv = sm + DINV_O;
    float* aggM = sm + AGG_O;
    float* aggS = aggM + 4;
    float* aggG = aggM + 8;
    float* misc = sm + MSC_O;

    const int tid = threadIdx.x;
    const int bx  = blockIdx.x;
    const int bh  = bx >> 4, c = bx & 15;
    const int b   = bh >> 3, h = bh & 7;
    const int gb  = (bh*Lq + c*CH)*hd;
    const int warp = tid >> 5, lane = tid & 31;

    // ---- phase A: gates/sims to smem, chunk-state prefix -> SP0 (tf32), misc ----
    if (tid < CH) {
        rawg[tid] = g_gate[bh*Lq + c*CH + tid];
        simA[tid] = g_sim [bh*Lq + c*CH + tid];
    }
    {
        int d = tid >> 3, e0 = (tid & 7)*4;
        float4 a = {0.f, 0.f, 0.f, 0.f};
        for (int cc = 0; cc < c; cc++) {
            float4 v = *(const float4*)&g_Sc[(bh*NCH + cc)*1024 + tid*4];
            a.x += v.x; a.y += v.y; a.z += v.z; a.w += v.w;
        }
        float* dst = &SP[d*40 + e0];
        dst[0]=tf32r(a.x); dst[1]=tf32r(a.y); dst[2]=tf32r(a.z); dst[3]=tf32r(a.w);
    }
    if (tid == 0) {
        float m = -1e30f, s = 0.f, ga = 0.f;
        for (int cc = 0; cc < c; cc++) {
            int i = bh*NCH + cc;
            float mc = g_mc[i], sc = g_scC[i];
            float mn = fmaxf(m, mc);
            s = s*__expf(m - mn) + sc*__expf(mc - mn);
            m = mn;
            ga += g_gsum[i];
        }
        misc[0] = m; misc[1] = s; misc[2] = ga;
    }
    __syncthreads();

    // ---- tile loads (Q, K, Vg=g*v), tf32 ----
    for (int idx = tid*4; idx < CH*hd; idx += 1024) {
        int i = idx >> 5, d = idx & 31;
        float g = rawg[i];
        float4 q4 = *(const float4*)&g_q[gb + idx];
        float4 v4 = *(const float4*)&g_v[gb + idx];
        float4 k4 = *(const float4*)&g_k[gb + idx];
        float* qd = &Qs[i*40 + d]; float* vd = &Vg[i*40 + d]; float* kd = &Ks[i*40 + d];
        qd[0]=tf32r(q4.x);   qd[1]=tf32r(q4.y);   qd[2]=tf32r(q4.z);   qd[3]=tf32r(q4.w);
        vd[0]=tf32r(v4.x*g); vd[1]=tf32r(v4.y*g); vd[2]=tf32r(v4.z*g); vd[3]=tf32r(v4.w*g);
        kd[0]=tf32r(k4.x);   kd[1]=tf32r(k4.y);   kd[2]=tf32r(k4.z);   kd[3]=tf32r(k4.w);
    }

    // ---- warp-shfl inclusive scans (softmax (m,s) and gate g) ----
    float mval = 0.f, sval = 0.f, gval = 0.f, sim0 = 0.f;
    if (tid < CH) {
        sim0 = simA[tid];
        mval = sim0; sval = 1.f; gval = rawg[tid];
        #pragma unroll
        for (int off = 1; off < 32; off <<= 1) {
            float m2 = __shfl_up_sync(0xffffffffu, mval, off);
            float s2 = __shfl_up_sync(0xffffffffu, sval, off);
            float g2 = __shfl_up_sync(0xffffffffu, gval, off);
            if (lane >= off) {
                float mn = fmaxf(mval, m2);
                sval = sval*__expf(mval - mn) + s2*__expf(m2 - mn);
                mval = mn;
                gval += g2;
            }
        }
        if (lane == 31) { aggM[warp] = mval; aggS[warp] = sval; aggG[warp] = gval; }
    }
    __syncthreads();
    if (tid < CH) {
        float mp = misc[0], sp = misc[1], gp = misc[2];
        for (int ww = 0; ww < warp; ww++) {
            float ma = aggM[ww], sa = aggS[ww];
            float mn = fmaxf(mp, ma);
            sp = sp*__expf(mp - mn) + sa*__expf(ma - mn);
            mp = mn;
            gp += aggG[ww];
        }
        float mn = fmaxf(mp, mval);
        float st = sp*__expf(mp - mn) + sval*__expf(mval - mn);
        float sw = __expf(sim0 - mn) / (st + EPSf);
        ws[tid]   = 1.f + sw / (1.f + __expf(-sw));
        dinv[tid] = 1.f / (gp + gval + EPSf);
    }

    // ---- Ssub_j = Vg_j^T @ K_j for j=0..2 (2 warps each: 4,5|6,7|0,1) ----
    {
        int task = -1;
        if (warp >= 4) task = warp - 4;          // j=0,1
        else if (warp < 2) task = 4 + warp;      // j=2
        if (task >= 0) {
            int j = task >> 1, hh = task & 1;    // hh: which 16 d-rows
            wmma::fragment<wmma::accumulator, 16, 16, 8, float> cs[2];
            wmma::fill_fragment(cs[0], 0.0f);
            wmma::fill_fragment(cs[1], 0.0f);
            #pragma unroll
            for (int kk = 0; kk < 4; kk++) {
                wmma::fragment<wmma::matrix_a, 16, 16, 8, wmma::precision::tf32, wmma::col_major> a;
                wmma::load_matrix_sync(a, &Vg[(j*32 + kk*8)*40 + hh*16], 40);
                #pragma unroll
                for (int jn = 0; jn < 2; jn++) {
                    wmma::fragment<wmma::matrix_b, 16, 16, 8, wmma::precision::tf32, wmma::row_major> bm;
                    wmma::load_matrix_sync(bm, &Ks[(j*32 + kk*8)*40 + jn*16], 40);
                    wmma::mma_sync(cs[jn], a, bm, cs[jn]);
                }
            }
            #pragma unroll
            for (int jn = 0; jn < 2; jn++)
                wmma::store_matrix_sync(&Pan[j*1280 + hh*16*40 + jn*16], cs[jn], 40, wmma::mem_row_major);
        }
    }
    __syncthreads();

    // ---- SP prefix: SP_{j+1} = tf32(Sps + sum_{<=j} Ssub) ----
    {
        int d = tid >> 3, e0 = (tid & 7)*4;
        int off = d*40 + e0;
        float a0 = SP[off+0], a1 = SP[off+1], a2 = SP[off+2], a3 = SP[off+3];
        #pragma unroll
        for (int j = 0; j < 3; j++) {
            a0 += Pan[j*1280 + off+0]; a1 += Pan[j*1280 + off+1];
            a2 += Pan[j*1280 + off+2]; a3 += Pan[j*1280 + off+3];
            float* dst = &SP[(j+1)*1280 + off];
            dst[0]=tf32r(a0); dst[1]=tf32r(a1); dst[2]=tf32r(a2); dst[3]=tf32r(a3);
        }
    }
    __syncthreads();

    // ---- per-warp output: rows [16w, 16w+16), sub-block sb = w/2 ----
    const int r0 = warp * 16, sb = warp >> 1;
    float* myPan = &Pan[warp*640];

    wmma::fragment<wmma::accumulator, 16, 16, 8, float> cY[2], cP[2];
    wmma::fill_fragment(cY[0], 0.0f); wmma::fill_fragment(cY[1], 0.0f);
    wmma::fill_fragment(cP[0], 0.0f); wmma::fill_fragment(cP[1], 0.0f);
    #pragma unroll
    for (int kk = 0; kk < 4; kk++) {
        wmma::fragment<wmma::matrix_a, 16, 16, 8, wmma::precision::tf32, wmma::row_major> a;
        wmma::load_matrix_sync(a, &Qs[r0*40 + kk*8], 40);
        #pragma unroll
        for (int jn = 0; jn < 2; jn++) {
            wmma::fragment<wmma::matrix_b, 16, 16, 8, wmma::precision::tf32, wmma::row_major> bS;
            wmma::load_matrix_sync(bS, &SP[sb*1280 + (kk*8)*40 + jn*16], 40);
            wmma::mma_sync(cY[jn], a, bS, cY[jn]);
            wmma::fragment<wmma::matrix_b, 16, 16, 8, wmma::precision::tf32, wmma::col_major> bV;
            wmma::load_matrix_sync(bV, &Vg[(sb*32 + jn*16)*40 + kk*8], 40);
            wmma::mma_sync(cP[jn], a, bV, cP[jn]);
        }
    }
    wmma::store_matrix_sync(&myPan[0],  cP[0], 40, wmma::mem_row_major);
    wmma::store_matrix_sync(&myPan[16], cP[1], 40, wmma::mem_row_major);
    __syncwarp();
    // mask: keep local col ii <= ((w&1)?16:0) + rr   (gate already in Vg)
    {
        int base_th = (warp & 1) << 4;
        #pragma unroll
        for (int e = 0; e < 16; e++) {
            int idx = lane + e*32;
            int rr = idx >> 5, ii = idx & 31;
            float val = myPan[rr*40 + ii];
            myPan[rr*40 + ii] = (ii <= base_th + rr) ? tf32r(val) : 0.f;
        }
    }
    __syncwarp();
    #pragma unroll
    for (int kk = 0; kk < 4; kk++) {
        wmma::fragment<wmma::matrix_a, 16, 16, 8, wmma::precision::tf32, wmma::row_major> a;
        wmma::load_matrix_sync(a, &myPan[kk*8], 40);
        #pragma unroll
        for (int jn = 0; jn < 2; jn++) {
            wmma::fragment<wmma::matrix_b, 16, 16, 8, wmma::precision::tf32, wmma::row_major> bm;
            wmma::load_matrix_sync(bm, &Ks[(sb*32 + kk*8)*40 + jn*16], 40);
            wmma::mma_sync(cY[jn], a, bm, cY[jn]);
        }
    }
    wmma::store_matrix_sync(&myPan[0],  cY[0], 40, wmma::mem_row_major);
    wmma::store_matrix_sync(&myPan[16], cY[1], 40, wmma::mem_row_major);
    __syncwarp();
    #pragma unroll
    for (int rr = 0; rr < 16; rr++) {
        int r = r0 + rr;
        float y = myPan[rr*40 + lane] * ws[r] * dinv[r];
        int cidx = (b*Lq + c*CH + r)*Dm + h*hd + lane;
        __half hy = __float2half_rn(y);
        d_ch[cidx] = hy;
        d_cl[cidx] = __float2half_rn(y - __half2float(hy));
    }
}

// ============================================================
// K4: output projection, pre-split fp16 + cp.async.
// ============================================================
#define STG2 20480
__global__ void k_out(const float* __restrict__ bo, float* __restrict__ out)
{
    extern __shared__ __align__(16) unsigned char smraw[];
    const unsigned sbase = (unsigned)__cvta_generic_to_shared(smraw);
    const int t  = threadIdx.x;
    const int m0 = blockIdx.x * 64;
    const int n0 = blockIdx.y * 64;
    const __half* Bgh = d_wh + 3*65536;
    const __half* Bgl = d_wl + 3*65536;
    const int warp = t >> 5;
    const int wm = warp >> 1, wn = warp & 1;

    wmma::fragment<wmma::accumulator, 16, 16, 16, float> c[2];
    wmma::fill_fragment(c[0], 0.0f);
    wmma::fill_fragment(c[1], 0.0f);

    auto issue = [&](int s, int k0) {
        unsigned sb = sbase + s*STG2;
        int row = t >> 2, seg = t & 3;
        unsigned so = row*80 + seg*16;
        int ga = (m0 + row)*256 + k0 + seg*8;
        int gbb = (n0 + row)*256 + k0 + seg*8;
        cpa16(sb + so,         d_ch + ga);
        cpa16(sb + 5120 + so,  d_cl + ga);
        cpa16(sb + 10240 + so, Bgh + gbb);
        cpa16(sb + 15360 + so, Bgl + gbb);
    };

    issue(0, 0); CP_COMMIT();
    int buf = 0;
    for (int it = 0; it < 8; it++) {
        if (it < 7) { issue(buf^1, (it+1)*32); CP_COMMIT(); CP_WAIT(1); }
        else        { CP_WAIT(0); }
        __syncthreads();
        const __half* Ah = (const __half*)(smraw + buf*STG2);
        const __half* Al = Ah + 2560;
        const __half* Bh = Ah + 5120;
        const __half* Bl = Ah + 7680;
        #pragma unroll
        for (int kk = 0; kk < 2; kk++) {
            wmma::fragment<wmma::matrix_a, 16, 16, 16, __half, wmma::row_major> ah, al;
            wmma::fragment<wmma::matrix_b, 16, 16, 16, __half, wmma::col_major> bh[2], bl[2];
            wmma::load_matrix_sync(ah, Ah + (wm*16)*40 + kk*16, 40);
            wmma::load_matrix_sync(al, Al + (wm*16)*40 + kk*16, 40);
            #pragma unroll
            for (int j = 0; j < 2; j++) {
                wmma::load_matrix_sync(bh[j], Bh + (wn*32 + j*16)*40 + kk*16, 40);
                wmma::load_matrix_sync(bl[j], Bl + (wn*32 + j*16)*40 + kk*16, 40);
            }
            #pragma unroll
            for (int j = 0; j < 2; j++) {
                wmma::mma_sync(c[j], ah, bh[j], c[j]);
                wmma::mma_sync(c[j], al, bh[j], c[j]);
                wmma::mma_sync(c[j], ah, bl[j], c[j]);
            }
        }
        __syncthreads();
        buf ^= 1;
    }
    float* Cs = (float*)smraw;
    #pragma unroll
    for (int j = 0; j < 2; j++)
        wmma::store_matrix_sync(&Cs[(wm*16)*64 + wn*32 + j*16], c[j], 64, wmma::mem_row_major);
    __syncthreads();
    for (int idx = t; idx < 64*64; idx += 256) {
        int row = idx >> 6, col = idx & 63;
        int o = n0 + col;
        out[(m0 + row)*256 + o] = Cs[idx] + bo[o];
    }
}

// ============================================================
extern "C" void kernel_launch(void* const* d_in, const int* in_sizes, int n_in,
                              void* d_out, int out_size)
{
    const float* x   = (const float*)d_in[0];
    const float* wq  = (const float*)d_in[1];
    const float* bq  = (const float*)d_in[2];
    const float* wk  = (const float*)d_in[3];
    const float* bk  = (const float*)d_in[4];
    const float* wv  = (const float*)d_in[5];
    const float* bv  = (const float*)d_in[6];
    const float* wo  = (const float*)d_in[7];
    const float* bo  = (const float*)d_in[8];
    const float* wg  = (const float*)d_in[9];
    const float* wgb = (const float*)d_in[10];
    const float* kvs = (const float*)d_in[11];
    const float* qks = (const float*)d_in[12];
    float* out = (float*)d_out;

    cudaFuncSetAttribute(k_qkv,   cudaFuncAttributeMaxDynamicSharedMemorySize, 2*STG1);
    cudaFuncSetAttribute(k_intra, cudaFuncAttributeMaxDynamicSharedMemorySize, SMEM_INTRA);
    cudaFuncSetAttribute(k_out,   cudaFuncAttributeMaxDynamicSharedMemorySize, 2*STG2);

    k_split    <<<1280, 256>>>(x, wq, wk, wv, wo);
    k_qkv      <<<dim3(32, 12), 256, 2*STG1>>>(bq, bk, bv);
    k_prepchunk<<<256, 256>>>(wg, wgb, kvs, qks);
    k_intra    <<<256, 256, SMEM_INTRA>>>();
    k_out      <<<dim3(64, 4), 256, 2*STG2>>>(bo, out);
}

// round 13
// speedup vs baseline: 2.6866x; 1.1236x over previous
#include <cuda_runtime.h>
#include <cuda_fp16.h>
#include <mma.h>
#include <math.h>

using namespace nvcuda;

#define Bsz 2
#define Lq  2048
#define Dm  256
#define Hh  8
#define hd  32
#define CH  128
#define NCH 16
#define BHn (Bsz*Hh)
#define EPSf 1e-5f

// ---- scratch (device globals; no allocations allowed) ----
__device__ float g_q[BHn*Lq*hd];
__device__ float g_k[BHn*Lq*hd];
__device__ float g_v[BHn*Lq*hd];
__device__ float g_sim[BHn*Lq];
__device__ float g_gate[BHn*Lq];
__device__ float g_Sc[BHn*NCH*hd*hd];
__device__ float g_gsum[BHn*NCH];
__device__ float g_mc[BHn*NCH];
__device__ float g_scC[BHn*NCH];
// pre-split fp16 hi/lo operands
__device__ __half d_xh[Bsz*Lq*Dm], d_xl[Bsz*Lq*Dm];       // x
__device__ __half d_wh[4*Dm*Dm],   d_wl[4*Dm*Dm];         // wq,wk,wv,wo
__device__ __half d_ch[Bsz*Lq*Dm], d_cl[Bsz*Lq*Dm];       // ctx

__device__ __forceinline__ float warpSum(float v) {
    #pragma unroll
    for (int o = 16; o; o >>= 1) v += __shfl_xor_sync(0xffffffffu, v, o);
    return v;
}
__device__ __forceinline__ float warpMax(float v) {
    #pragma unroll
    for (int o = 16; o; o >>= 1) v = fmaxf(v, __shfl_xor_sync(0xffffffffu, v, o));
    return v;
}
__device__ __forceinline__ float tf32r(float f) { return wmma::__float_to_tf32(f); }

__device__ __forceinline__ void cpa16(unsigned sa, const void* g) {
    asm volatile("cp.async.ca.shared.global [%0], [%1], 16;" :: "r"(sa), "l"(g));
}
#define CP_COMMIT()  asm volatile("cp.async.commit_group;")
#define CP_WAIT(n)   asm volatile("cp.async.wait_group %0;" :: "n"(n))

// ============================================================
// K0: split x and the four weight matrices into fp16 hi/lo.
// ============================================================
__global__ void k_split(const float* __restrict__ x,
                        const float* __restrict__ wq, const float* __restrict__ wk,
                        const float* __restrict__ wv, const float* __restrict__ wo)
{
    int i = blockIdx.x*256 + threadIdx.x;
    const float4* src;
    __half *dh, *dl;
    if (i < 262144) {
        src = (const float4*)x + i;
        dh = d_xh + i*4; dl = d_xl + i*4;
    } else {
        int j = i - 262144;
        int w = j >> 14, off = j & 16383;
        const float* ws = (w==0)?wq:((w==1)?wk:((w==2)?wv:wo));
        src = (const float4*)ws + off;
        dh = d_wh + w*65536 + off*4; dl = d_wl + w*65536 + off*4;
    }
    float4 f = *src;
    __half h0=__float2half_rn(f.x), h1=__float2half_rn(f.y),
           h2=__float2half_rn(f.z), h3=__float2half_rn(f.w);
    ((__half2*)dh)[0] = __halves2half2(h0, h1);
    ((__half2*)dh)[1] = __halves2half2(h2, h3);
    ((__half2*)dl)[0] = __halves2half2(__float2half_rn(f.x-__half2float(h0)),
                                       __float2half_rn(f.y-__half2float(h1)));
    ((__half2*)dl)[1] = __halves2half2(__float2half_rn(f.z-__half2float(h2)),
                                       __float2half_rn(f.w-__half2float(h3)));
}

// ============================================================
// K1: QKV projection, pre-split fp16, cp.async 2-stage pipeline.
// ============================================================
#define STG1 30720
__global__ void k_qkv(const float* __restrict__ bq, const float* __restrict__ bk,
                      const float* __restrict__ bv)
{
    extern __shared__ __align__(16) unsigned char smraw[];
    const unsigned sbase = (unsigned)__cvta_generic_to_shared(smraw);
    const int t   = threadIdx.x;
    const int m0  = blockIdx.x * 128;
    const int mat = blockIdx.y >> 2;
    const int n0  = (blockIdx.y & 3) * 64;
    const __half* Bgh = d_wh + mat*65536;
    const __half* Bgl = d_wl + mat*65536;
    const float* bias = (mat == 0) ? bq : ((mat == 1) ? bk : bv);
    const int warp = t >> 5;
    const int wm = warp >> 1, wn = warp & 1;

    wmma::fragment<wmma::accumulator, 16, 16, 16, float> c[2][2];
    #pragma unroll
    for (int i = 0; i < 2; i++)
        #pragma unroll
        for (int j = 0; j < 2; j++) wmma::fill_fragment(c[i][j], 0.0f);

    auto issue = [&](int s, int k0) {
        unsigned sb = sbase + s*STG1;
        #pragma unroll
        for (int p = 0; p < 2; p++) {
            int slot = t + p*256;
            int row = slot >> 2, seg = slot & 3;
            int go = (m0 + row)*256 + k0 + seg*8;
            unsigned so = row*80 + seg*16;
            cpa16(sb + so,         d_xh + go);
            cpa16(sb + 10240 + so, d_xl + go);
        }
        {
            int row = t >> 2, seg = t & 3;
            int go = (n0 + row)*256 + k0 + seg*8;
            unsigned so = row*80 + seg*16;
            cpa16(sb + 20480 + so, Bgh + go);
            cpa16(sb + 25600 + so, Bgl + go);
        }
    };

    issue(0, 0); CP_COMMIT();
    int buf = 0;
    for (int it = 0; it < 8; it++) {
        if (it < 7) { issue(buf^1, (it+1)*32); CP_COMMIT(); CP_WAIT(1); }
        else        { CP_WAIT(0); }
        __syncthreads();
        const __half* Ah = (const __half*)(smraw + buf*STG1);
        const __half* Al = Ah + 5120;
        const __half* Bh = Ah + 10240;
        const __half* Bl = Ah + 12800;
        #pragma unroll
        for (int kk = 0; kk < 2; kk++) {
            wmma::fragment<wmma::matrix_a, 16, 16, 16, __half, wmma::row_major> ah[2], al[2];
            wmma::fragment<wmma::matrix_b, 16, 16, 16, __half, wmma::col_major> bh[2], bl[2];
            #pragma unroll
            for (int i = 0; i < 2; i++) {
                wmma::load_matrix_sync(ah[i], Ah + (wm*32 + i*16)*40 + kk*16, 40);
                wmma::load_matrix_sync(al[i], Al + (wm*32 + i*16)*40 + kk*16, 40);
            }
            #pragma unroll
            for (int j = 0; j < 2; j++) {
                wmma::load_matrix_sync(bh[j], Bh + (wn*32 + j*16)*40 + kk*16, 40);
                wmma::load_matrix_sync(bl[j], Bl + (wn*32 + j*16)*40 + kk*16, 40);
            }
            #pragma unroll
            for (int i = 0; i < 2; i++)
                #pragma unroll
                for (int j = 0; j < 2; j++) {
                    wmma::mma_sync(c[i][j], ah[i], bh[j], c[i][j]);
                    wmma::mma_sync(c[i][j], al[i], bh[j], c[i][j]);
                    wmma::mma_sync(c[i][j], ah[i], bl[j], c[i][j]);
                }
        }
        __syncthreads();
        buf ^= 1;
    }
    float* Cs = (float*)smraw;
    #pragma unroll
    for (int i = 0; i < 2; i++)
        #pragma unroll
        for (int j = 0; j < 2; j++)
            wmma::store_matrix_sync(&Cs[(wm*32 + i*16)*64 + wn*32 + j*16], c[i][j], 64, wmma::mem_row_major);
    __syncthreads();
    float* dst = (mat == 0) ? g_q : ((mat == 1) ? g_k : g_v);
    for (int idx = t; idx < 128*64; idx += 256) {
        int row = idx >> 6, col = idx & 63;
        int m = m0 + row;
        int b = m >> 11, l = m & 2047;
        int o = n0 + col;
        int hidx = o >> 5, d = o & 31;
        dst[((b*Hh + hidx)*Lq + l)*hd + d] = Cs[idx] + bias[o];
    }
}

// ============================================================
// K2: preprocess, restructured: thread-pair per position,
//     tensor-core gate (T = K̂ @ M^T), then chunk sums.
// grid: 256 blocks, 256 threads. dyn smem 58880 B:
//   Ksh 128x36 | Vsh 128x36 | Msh 32x36 | Tsh 128x32 | gs 128 | sims 128
// ============================================================
#define PREP_SMEM 58880
__global__ void k_prepchunk(const float* __restrict__ wg, const float* __restrict__ wgb,
                            const float* __restrict__ kvs, const float* __restrict__ qks)
{
    extern __shared__ float ps[];
    float* Ksh = ps;
    float* Vsh = ps + 4608;
    float* Msh = ps + 9216;
    float* Tsh = ps + 10368;
    float* gsh = ps + 14464;
    float* ssh = ps + 14592;
    const int tid = threadIdx.x;
    const int bx = blockIdx.x, bh = bx >> 4, c = bx & 15, h = bh & 7;
    const int warp = tid >> 5;

    for (int idx = tid; idx < 1024; idx += 256) {
        int d = idx >> 5, e = idx & 31;
        Msh[d*36 + e] = tf32r(kvs[h*1024 + idx] * wg[idx]);
    }
    const float qscale = qks[h];
    const float wb0 = wgb[0];
    const int pos = tid >> 1, hf = tid & 1;
    const int gbase = (bh*Lq + c*CH + pos)*hd + hf*16;

    float4 kr[4], vr[4];
    float qk = 0.f, kk = 0.f, vv = 0.f;
    #pragma unroll
    for (int j = 0; j < 4; j++) {
        float4 q4 = *(const float4*)&g_q[gbase + j*4];
        kr[j] = *(const float4*)&g_k[gbase + j*4];
        vr[j] = *(const float4*)&g_v[gbase + j*4];
        qk += q4.x*kr[j].x + q4.y*kr[j].y + q4.z*kr[j].z + q4.w*kr[j].w;
        kk += kr[j].x*kr[j].x + kr[j].y*kr[j].y + kr[j].z*kr[j].z + kr[j].w*kr[j].w;
        vv += vr[j].x*vr[j].x + vr[j].y*vr[j].y + vr[j].z*vr[j].z + vr[j].w*vr[j].w;
    }
    qk += __shfl_xor_sync(0xffffffffu, qk, 1);
    kk += __shfl_xor_sync(0xffffffffu, kk, 1);
    vv += __shfl_xor_sync(0xffffffffu, vv, 1);
    float sim = qk * qscale;
    float kin = 1.f / fmaxf(sqrtf(kk), 1e-12f);
    float vin = 1.f / fmaxf(sqrtf(vv), 1e-12f);
    #pragma unroll
    for (int j = 0; j < 4; j++) {
        kr[j].x *= kin; kr[j].y *= kin; kr[j].z *= kin; kr[j].w *= kin;
        vr[j].x *= vin; vr[j].y *= vin; vr[j].z *= vin; vr[j].w *= vin;
        *(float4*)&g_k[gbase + j*4] = kr[j];
        *(float4*)&g_v[gbase + j*4] = vr[j];
        float* kd = &Ksh[pos*36 + hf*16 + j*4];
        kd[0]=tf32r(kr[j].x); kd[1]=tf32r(kr[j].y); kd[2]=tf32r(kr[j].z); kd[3]=tf32r(kr[j].w);
        float* vd = &Vsh[pos*36 + hf*16 + j*4];
        vd[0]=tf32r(vr[j].x); vd[1]=tf32r(vr[j].y); vd[2]=tf32r(vr[j].z); vd[3]=tf32r(vr[j].w);
    }
    if (hf == 0) { ssh[pos] = sim; g_sim[bh*Lq + c*CH + pos] = sim; }
    __syncthreads();

    // T = K̂ @ M^T  (8 warps x 16 rows)
    {
        wmma::fragment<wmma::accumulator, 16, 16, 8, float> ct[2];
        wmma::fill_fragment(ct[0], 0.f); wmma::fill_fragment(ct[1], 0.f);
        #pragma unroll
        for (int ks = 0; ks < 4; ks++) {
            wmma::fragment<wmma::matrix_a, 16, 16, 8, wmma::precision::tf32, wmma::row_major> a;
            wmma::load_matrix_sync(a, &Ksh[(warp*16)*36 + ks*8], 36);
            #pragma unroll
            for (int jn = 0; jn < 2; jn++) {
                wmma::fragment<wmma::matrix_b, 16, 16, 8, wmma::precision::tf32, wmma::col_major> bm;
                wmma::load_matrix_sync(bm, &Msh[(jn*16)*36 + ks*8], 36);
                wmma::mma_sync(ct[jn], a, bm, ct[jn]);
            }
        }
        wmma::store_matrix_sync(&Tsh[(warp*16)*32 + 0],  ct[0], 32, wmma::mem_row_major);
        wmma::store_matrix_sync(&Tsh[(warp*16)*32 + 16], ct[1], 32, wmma::mem_row_major);
    }
    __syncthreads();

    // gate_i = relu(v̂·T_i + b)^2 + eps
    {
        float dot = 0.f;
        #pragma unroll
        for (int j = 0; j < 4; j++) {
            float4 t4 = *(const float4*)&Tsh[pos*32 + hf*16 + j*4];
            float4 v4 = *(const float4*)&Vsh[pos*36 + hf*16 + j*4];
            dot += t4.x*v4.x + t4.y*v4.y + t4.z*v4.z + t4.w*v4.w;
        }
        dot += __shfl_xor_sync(0xffffffffu, dot, 1);
        if (hf == 0) {
            float r = fmaxf(dot + wb0, 0.f);
            float gate = r*r + EPSf;
            gsh[pos] = gate;
            g_gate[bh*Lq + c*CH + pos] = gate;
        }
    }
    __syncthreads();

    // chunk outer product + stats
    const int d = tid >> 3, e0 = (tid & 7)*4;
    float4 acc = {0.f, 0.f, 0.f, 0.f};
    for (int i = 0; i < CH; i++) {
        float cfv = gsh[i] * Vsh[i*36 + d];
        float4 k4 = *(const float4*)&Ksh[i*36 + e0];
        acc.x += cfv*k4.x; acc.y += cfv*k4.y; acc.z += cfv*k4.z; acc.w += cfv*k4.w;
    }
    *(float4*)&g_Sc[bx*1024 + tid*4] = acc;
    if (tid < 32) {
        float m = -1e30f;
        #pragma unroll
        for (int k = 0; k < 4; k++) m = fmaxf(m, ssh[tid + 32*k]);
        m = warpMax(m);
        float s = 0.f, gsum = 0.f;
        #pragma unroll
        for (int k = 0; k < 4; k++) { s += __expf(ssh[tid + 32*k] - m); gsum += gsh[tid + 32*k]; }
        s = warpSum(s); gsum = warpSum(gsum);
        if (tid == 0) { g_mc[bx] = m; g_scC[bx] = s; g_gsum[bx] = gsum; }
    }
}

// ============================================================
// K3: intra-chunk (front-loaded LDGs + warp-parallel misc).
// ============================================================
#define QS_O   0
#define VG_O   5120
#define KS_O   10240
#define SP_O   15360
#define PAN_O  20480
#define RAWG_O 25600
#define SIMA_O 25728
#define WS_O   25856
#define DINV_O 25984
#define AGG_O  26112
#define MSC_O  26124
#define SMEM_INTRA ((MSC_O + 4) * 4)

__global__ void k_intra()
{
    extern __shared__ float sm[];
    float* Qs   = sm + QS_O;
    float* Vg   = sm + VG_O;
    float* Ks   = sm + KS_O;
    float* SP   = sm + SP_O;
    float* Pan  = sm + PAN_O;
    float* rawg = sm + RAWG_O;
    float* simA = sm + SIMA_O;
    float* ws   = sm + WS_O;
    float* dinv = sm + DINV_O;
    float* aggM = sm + AGG_O;
    float* aggS = aggM + 4;
    float* aggG = aggM + 8;
    float* misc = sm + MSC_O;

    const int tid = threadIdx.x;
    const int bx  = blockIdx.x;
    const int bh  = bx >> 4, c = bx & 15;
    const int b   = bh >> 3, h = bh & 7;
    const int gb  = (bh*Lq + c*CH)*hd;
    const int warp = tid >> 5, lane = tid & 31;

    // ---- front-loaded tile LDGs; Q,K stored immediately, V persists ----
    float4 vr[4];
    #pragma unroll
    for (int p = 0; p < 4; p++) {
        int idx = tid*4 + p*1024;
        float4 q4 = *(const float4*)&g_q[gb + idx];
        float4 k4 = *(const float4*)&g_k[gb + idx];
        vr[p]     = *(const float4*)&g_v[gb + idx];
        int i = idx >> 5, dd = idx & 31;
        float* qd = &Qs[i*40 + dd];
        qd[0]=tf32r(q4.x); qd[1]=tf32r(q4.y); qd[2]=tf32r(q4.z); qd[3]=tf32r(q4.w);
        float* kd = &Ks[i*40 + dd];
        kd[0]=tf32r(k4.x); kd[1]=tf32r(k4.y); kd[2]=tf32r(k4.z); kd[3]=tf32r(k4.w);
    }
    if (tid < CH) {
        rawg[tid] = g_gate[bh*Lq + c*CH + tid];
        simA[tid] = g_sim [bh*Lq + c*CH + tid];
    }
    // chunk-state exclusive prefix -> SP0
    {
        int d = tid >> 3, e0 = (tid & 7)*4;
        float4 a = {0.f, 0.f, 0.f, 0.f};
        for (int cc = 0; cc < c; cc++) {
            float4 v = *(const float4*)&g_Sc[(bh*NCH + cc)*1024 + tid*4];
            a.x += v.x; a.y += v.y; a.z += v.z; a.w += v.w;
        }
        float* dst = &SP[d*40 + e0];
        dst[0]=tf32r(a.x); dst[1]=tf32r(a.y); dst[2]=tf32r(a.z); dst[3]=tf32r(a.w);
    }
    // misc: warp-parallel order-independent softmax/gate combine over chunks < c
    if (warp == 0) {
        float mc = -1e30f, sc = 0.f, gg = 0.f;
        if (lane < c) {
            int i = bh*NCH + lane;
            mc = g_mc[i]; sc = g_scC[i]; gg = g_gsum[i];
        }
        float m  = warpMax(mc);
        float s  = warpSum(sc * __expf(mc - m));
        float gp = warpSum(gg);
        if (lane == 0) { misc[0] = m; misc[1] = s; misc[2] = gp; }
    }
    __syncthreads();

    // Vg = g * v (rawg now visible)
    #pragma unroll
    for (int p = 0; p < 4; p++) {
        int idx = tid*4 + p*1024;
        int i = idx >> 5, dd = idx & 31;
        float g = rawg[i];
        float* vd = &Vg[i*40 + dd];
        vd[0]=tf32r(vr[p].x*g); vd[1]=tf32r(vr[p].y*g);
        vd[2]=tf32r(vr[p].z*g); vd[3]=tf32r(vr[p].w*g);
    }

    // ---- warp-shfl inclusive scans ----
    float mval = 0.f, sval = 0.f, gval = 0.f, sim0 = 0.f;
    if (tid < CH) {
        sim0 = simA[tid];
        mval = sim0; sval = 1.f; gval = rawg[tid];
        #pragma unroll
        for (int off = 1; off < 32; off <<= 1) {
            float m2 = __shfl_up_sync(0xffffffffu, mval, off);
            float s2 = __shfl_up_sync(0xffffffffu, sval, off);
            float g2 = __shfl_up_sync(0xffffffffu, gval, off);
            if (lane >= off) {
                float mn = fmaxf(mval, m2);
                sval = sval*__expf(mval - mn) + s2*__expf(m2 - mn);
                mval = mn;
                gval += g2;
            }
        }
        if (lane == 31) { aggM[warp] = mval; aggS[warp] = sval; aggG[warp] = gval; }
    }
    __syncthreads();
    if (tid < CH) {
        float mp = misc[0], sp = misc[1], gp = misc[2];
        for (int ww = 0; ww < warp; ww++) {
            float ma = aggM[ww], sa = aggS[ww];
            float mn = fmaxf(mp, ma);
            sp = sp*__expf(mp - mn) + sa*__expf(ma - mn);
            mp = mn;
            gp += aggG[ww];
        }
        float mn = fmaxf(mp, mval);
        float st = sp*__expf(mp - mn) + sval*__expf(mval - mn);
        float sw = __expf(sim0 - mn) / (st + EPSf);
        ws[tid]   = 1.f + sw / (1.f + __expf(-sw));
        dinv[tid] = 1.f / (gp + gval + EPSf);
    }

    // ---- Ssub_j = Vg_j^T @ K_j for j=0..2 (2 warps each: 4,5|6,7|0,1) ----
    {
        int task = -1;
        if (warp >= 4) task = warp - 4;
        else if (warp < 2) task = 4 + warp;
        if (task >= 0) {
            int j = task >> 1, hh = task & 1;
            wmma::fragment<wmma::accumulator, 16, 16, 8, float> cs[2];
            wmma::fill_fragment(cs[0], 0.0f);
            wmma::fill_fragment(cs[1], 0.0f);
            #pragma unroll
            for (int kk = 0; kk < 4; kk++) {
                wmma::fragment<wmma::matrix_a, 16, 16, 8, wmma::precision::tf32, wmma::col_major> a;
                wmma::load_matrix_sync(a, &Vg[(j*32 + kk*8)*40 + hh*16], 40);
                #pragma unroll
                for (int jn = 0; jn < 2; jn++) {
                    wmma::fragment<wmma::matrix_b, 16, 16, 8, wmma::precision::tf32, wmma::row_major> bm;
                    wmma::load_matrix_sync(bm, &Ks[(j*32 + kk*8)*40 + jn*16], 40);
                    wmma::mma_sync(cs[jn], a, bm, cs[jn]);
                }
            }
            #pragma unroll
            for (int jn = 0; jn < 2; jn++)
                wmma::store_matrix_sync(&Pan[j*1280 + hh*16*40 + jn*16], cs[jn], 40, wmma::mem_row_major);
        }
    }
    __syncthreads();

    // ---- SP prefix ----
    {
        int d = tid >> 3, e0 = (tid & 7)*4;
        int off = d*40 + e0;
        float a0 = SP[off+0], a1 = SP[off+1], a2 = SP[off+2], a3 = SP[off+3];
        #pragma unroll
        for (int j = 0; j < 3; j++) {
            a0 += Pan[j*1280 + off+0]; a1 += Pan[j*1280 + off+1];
            a2 += Pan[j*1280 + off+2]; a3 += Pan[j*1280 + off+3];
            float* dst = &SP[(j+1)*1280 + off];
            dst[0]=tf32r(a0); dst[1]=tf32r(a1); dst[2]=tf32r(a2); dst[3]=tf32r(a3);
        }
    }
    __syncthreads();

    // ---- per-warp output ----
    const int r0 = warp * 16, sb = warp >> 1;
    float* myPan = &Pan[warp*640];

    wmma::fragment<wmma::accumulator, 16, 16, 8, float> cY[2], cP[2];
    wmma::fill_fragment(cY[0], 0.0f); wmma::fill_fragment(cY[1], 0.0f);
    wmma::fill_fragment(cP[0], 0.0f); wmma::fill_fragment(cP[1], 0.0f);
    #pragma unroll
    for (int kk = 0; kk < 4; kk++) {
        wmma::fragment<wmma::matrix_a, 16, 16, 8, wmma::precision::tf32, wmma::row_major> a;
        wmma::load_matrix_sync(a, &Qs[r0*40 + kk*8], 40);
        #pragma unroll
        for (int jn = 0; jn < 2; jn++) {
            wmma::fragment<wmma::matrix_b, 16, 16, 8, wmma::precision::tf32, wmma::row_major> bS;
            wmma::load_matrix_sync(bS, &SP[sb*1280 + (kk*8)*40 + jn*16], 40);
            wmma::mma_sync(cY[jn], a, bS, cY[jn]);
            wmma::fragment<wmma::matrix_b, 16, 16, 8, wmma::precision::tf32, wmma::col_major> bV;
            wmma::load_matrix_sync(bV, &Vg[(sb*32 + jn*16)*40 + kk*8], 40);
            wmma::mma_sync(cP[jn], a, bV, cP[jn]);
        }
    }
    wmma::store_matrix_sync(&myPan[0],  cP[0], 40, wmma::mem_row_major);
    wmma::store_matrix_sync(&myPan[16], cP[1], 40, wmma::mem_row_major);
    __syncwarp();
    {
        int base_th = (warp & 1) << 4;
        #pragma unroll
        for (int e = 0; e < 16; e++) {
            int idx = lane + e*32;
            int rr = idx >> 5, ii = idx & 31;
            float val = myPan[rr*40 + ii];
            myPan[rr*40 + ii] = (ii <= base_th + rr) ? tf32r(val) : 0.f;
        }
    }
    __syncwarp();
    #pragma unroll
    for (int kk = 0; kk < 4; kk++) {
        wmma::fragment<wmma::matrix_a, 16, 16, 8, wmma::precision::tf32, wmma::row_major> a;
        wmma::load_matrix_sync(a, &myPan[kk*8], 40);
        #pragma unroll
        for (int jn = 0; jn < 2; jn++) {
            wmma::fragment<wmma::matrix_b, 16, 16, 8, wmma::precision::tf32, wmma::row_major> bm;
            wmma::load_matrix_sync(bm, &Ks[(sb*32 + kk*8)*40 + jn*16], 40);
            wmma::mma_sync(cY[jn], a, bm, cY[jn]);
        }
    }
    wmma::store_matrix_sync(&myPan[0],  cY[0], 40, wmma::mem_row_major);
    wmma::store_matrix_sync(&myPan[16], cY[1], 40, wmma::mem_row_major);
    __syncwarp();
    #pragma unroll
    for (int rr = 0; rr < 16; rr++) {
        int r = r0 + rr;
        float y = myPan[rr*40 + lane] * ws[r] * dinv[r];
        int cidx = (b*Lq + c*CH + r)*Dm + h*hd + lane;
        __half hy = __float2half_rn(y);
        d_ch[cidx] = hy;
        d_cl[cidx] = __float2half_rn(y - __half2float(hy));
    }
}

// ============================================================
// K4: output projection, pre-split fp16 + cp.async.
// ============================================================
#define STG2 20480
__global__ void k_out(const float* __restrict__ bo, float* __restrict__ out)
{
    extern __shared__ __align__(16) unsigned char smraw[];
    const unsigned sbase = (unsigned)__cvta_generic_to_shared(smraw);
    const int t  = threadIdx.x;
    const int m0 = blockIdx.x * 64;
    const int n0 = blockIdx.y * 64;
    const __half* Bgh = d_wh + 3*65536;
    const __half* Bgl = d_wl + 3*65536;
    const int warp = t >> 5;
    const int wm = warp >> 1, wn = warp & 1;

    wmma::fragment<wmma::accumulator, 16, 16, 16, float> c[2];
    wmma::fill_fragment(c[0], 0.0f);
    wmma::fill_fragment(c[1], 0.0f);

    auto issue = [&](int s, int k0) {
        unsigned sb = sbase + s*STG2;
        int row = t >> 2, seg = t & 3;
        unsigned so = row*80 + seg*16;
        int ga = (m0 + row)*256 + k0 + seg*8;
        int gbb = (n0 + row)*256 + k0 + seg*8;
        cpa16(sb + so,         d_ch + ga);
        cpa16(sb + 5120 + so,  d_cl + ga);
        cpa16(sb + 10240 + so, Bgh + gbb);
        cpa16(sb + 15360 + so, Bgl + gbb);
    };

    issue(0, 0); CP_COMMIT();
    int buf = 0;
    for (int it = 0; it < 8; it++) {
        if (it < 7) { issue(buf^1, (it+1)*32); CP_COMMIT(); CP_WAIT(1); }
        else        { CP_WAIT(0); }
        __syncthreads();
        const __half* Ah = (const __half*)(smraw + buf*STG2);
        const __half* Al = Ah + 2560;
        const __half* Bh = Ah + 5120;
        const __half* Bl = Ah + 7680;
        #pragma unroll
        for (int kk = 0; kk < 2; kk++) {
            wmma::fragment<wmma::matrix_a, 16, 16, 16, __half, wmma::row_major> ah, al;
            wmma::fragment<wmma::matrix_b, 16, 16, 16, __half, wmma::col_major> bh[2], bl[2];
            wmma::load_matrix_sync(ah, Ah + (wm*16)*40 + kk*16, 40);
            wmma::load_matrix_sync(al, Al + (wm*16)*40 + kk*16, 40);
            #pragma unroll
            for (int j = 0; j < 2; j++) {
                wmma::load_matrix_sync(bh[j], Bh + (wn*32 + j*16)*40 + kk*16, 40);
                wmma::load_matrix_sync(bl[j], Bl + (wn*32 + j*16)*40 + kk*16, 40);
            }
            #pragma unroll
            for (int j = 0; j < 2; j++) {
                wmma::mma_sync(c[j], ah, bh[j], c[j]);
                wmma::mma_sync(c[j], al, bh[j], c[j]);
                wmma::mma_sync(c[j], ah, bl[j], c[j]);
            }
        }
        __syncthreads();
        buf ^= 1;
    }
    float* Cs = (float*)smraw;
    #pragma unroll
    for (int j = 0; j < 2; j++)
        wmma::store_matrix_sync(&Cs[(wm*16)*64 + wn*32 + j*16], c[j], 64, wmma::mem_row_major);
    __syncthreads();
    for (int idx = t; idx < 64*64; idx += 256) {
        int row = idx >> 6, col = idx & 63;
        int o = n0 + col;
        out[(m0 + row)*256 + o] = Cs[idx] + bo[o];
    }
}

// ============================================================
extern "C" void kernel_launch(void* const* d_in, const int* in_sizes, int n_in,
                              void* d_out, int out_size)
{
    const float* x   = (const float*)d_in[0];
    const float* wq  = (const float*)d_in[1];
    const float* bq  = (const float*)d_in[2];
    const float* wk  = (const float*)d_in[3];
    const float* bk  = (const float*)d_in[4];
    const float* wv  = (const float*)d_in[5];
    const float* bv  = (const float*)d_in[6];
    const float* wo  = (const float*)d_in[7];
    const float* bo  = (const float*)d_in[8];
    const float* wg  = (const float*)d_in[9];
    const float* wgb = (const float*)d_in[10];
    const float* kvs = (const float*)d_in[11];
    const float* qks = (const float*)d_in[12];
    float* out = (float*)d_out;

    cudaFuncSetAttribute(k_qkv,       cudaFuncAttributeMaxDynamicSharedMemorySize, 2*STG1);
    cudaFuncSetAttribute(k_prepchunk, cudaFuncAttributeMaxDynamicSharedMemorySize, PREP_SMEM);
    cudaFuncSetAttribute(k_intra,     cudaFuncAttributeMaxDynamicSharedMemorySize, SMEM_INTRA);
    cudaFuncSetAttribute(k_out,       cudaFuncAttributeMaxDynamicSharedMemorySize, 2*STG2);

    k_split    <<<1280, 256>>>(x, wq, wk, wv, wo);
    k_qkv      <<<dim3(32, 12), 256, 2*STG1>>>(bq, bk, bv);
    k_prepchunk<<<256, 256, PREP_SMEM>>>(wg, wgb, kvs, qks);
    k_intra    <<<256, 256, SMEM_INTRA>>>();
    k_out      <<<dim3(64, 4), 256, 2*STG2>>>(bo, out);
}